// round 2
// baseline (speedup 1.0000x reference)
#include <cuda_runtime.h>
#include <cuda_bf16.h>
#include <math.h>

// Problem constants
#define BB 2
#define SS 4096
#define DD 1024
#define HH 16
#define HDIM 64
#define MM 512
#define LL 1024          // 2*MM
#define HID 2816
#define NSTEP 8          // SS/MM

// ---------------- scratch (device globals; no allocation allowed) ----------------
__device__ float g_Y  [BB * SS * DD];   // attention outputs / om chain (32MB)
__device__ float g_Q  [BB * LL * DD];   // q buffer (only rows M..L used)
__device__ float g_K  [BB * LL * DD];
__device__ float g_V  [BB * LL * DD];
__device__ float g_OM2[BB * MM * DD];
__device__ float g_HN [BB * MM * DD];
__device__ float g_H1 [BB * MM * HID];
__device__ float g_H3 [BB * MM * HID];
__device__ float g_OMN[BB * MM * DD];

// ---------------- SGEMM: C[row,col] (+)= sum_k A[row,k]*B[k,col] ----------------
// Multi-output: up to 3 sub-GEMMs sharing A, each with its own B and C of width
// Nper. sel = blockIdx.x / nbper picks the sub-GEMM. Tiles: 64 (M) x 128 (N),
// BK=8, 256 threads, 4x8 per thread, double-buffered smem.
// Row mapping (batched slices without copies):
//   A index = (r / Mchunk)*a_bs + ((r % Mchunk) + a_off)*K
//   C index = (r / Mchunk)*c_bs + ((r % Mchunk) + c_off)*Nper
#define BM 64
#define BN 128
#define BKT 8

__global__ __launch_bounds__(256, 2) void sgemm_kernel(
    const float* __restrict__ A,
    const float* __restrict__ B0, const float* __restrict__ B1, const float* __restrict__ B2,
    float* __restrict__ C0, float* __restrict__ C1, float* __restrict__ C2,
    int Nper, int K, int nbper,
    long long a_bs, int a_off, int Mchunk,
    long long c_bs, int c_off, int acc)
{
    __shared__ float As[2][BKT][BM + 4];   // stride 68: conflict-free, 16B-aligned rows
    __shared__ float Bs[2][BKT][BN];

    int tid = threadIdx.x;
    int sel = blockIdx.x / nbper;
    int block_n = (blockIdx.x - sel * nbper) * BN;
    int block_m = blockIdx.y * BM;
    const float* B = (sel == 0) ? B0 : ((sel == 1) ? B1 : B2);
    float*       C = (sel == 0) ? C0 : ((sel == 1) ? C1 : C2);

    // A loader: threads 0..127 load one float4 each (row tid>>1, k-offset (tid&1)*4)
    int a_row = tid >> 1;            // 0..127 (used if <128 threads -> rows 0..63)
    int a_k   = (tid & 1) << 2;      // 0 or 4
    int gr    = block_m + (a_row & 63);
    const float* a_ptr = A + (long long)(gr / Mchunk) * a_bs
                           + (long long)((gr % Mchunk) + a_off) * K + a_k;
    // B loader: every thread one float4 (k = tid>>5, col = (tid&31)*4)
    int b_k = tid >> 5;              // 0..7
    int b_c = (tid & 31) << 2;
    const float* b_ptr = B + (long long)b_k * Nper + block_n + b_c;

    int tx = tid & 15, ty = tid >> 4;
    int m0 = ty << 2, n0 = tx << 2;

    float accv[4][8];
    #pragma unroll
    for (int i = 0; i < 4; i++)
        #pragma unroll
        for (int j = 0; j < 8; j++) accv[i][j] = 0.f;

    // preload k-slab 0
    float4 av, bv;
    if (tid < 128) av = *(const float4*)(a_ptr);
    bv = *(const float4*)(b_ptr);
    if (tid < 128) {
        As[0][a_k + 0][a_row & 63] = av.x;
        As[0][a_k + 1][a_row & 63] = av.y;
        As[0][a_k + 2][a_row & 63] = av.z;
        As[0][a_k + 3][a_row & 63] = av.w;
    }
    *(float4*)&Bs[0][b_k][b_c] = bv;
    __syncthreads();

    int cur = 0;
    for (int k0 = 0; k0 < K; k0 += BKT) {
        int kn = k0 + BKT;
        float4 nav, nbv;
        bool hn = kn < K;
        if (hn) {
            if (tid < 128) nav = *(const float4*)(a_ptr + kn);
            nbv = *(const float4*)(b_ptr + (long long)kn * Nper);
        }
        #pragma unroll
        for (int k = 0; k < BKT; k++) {
            float4 aA = *(const float4*)&As[cur][k][m0];
            float4 bA = *(const float4*)&Bs[cur][k][n0];
            float4 bB = *(const float4*)&Bs[cur][k][n0 + 64];
            float ar[4] = {aA.x, aA.y, aA.z, aA.w};
            float br[8] = {bA.x, bA.y, bA.z, bA.w, bB.x, bB.y, bB.z, bB.w};
            #pragma unroll
            for (int i = 0; i < 4; i++)
                #pragma unroll
                for (int j = 0; j < 8; j++)
                    accv[i][j] += ar[i] * br[j];
        }
        if (hn) {
            int nxt = cur ^ 1;
            if (tid < 128) {
                As[nxt][a_k + 0][a_row & 63] = nav.x;
                As[nxt][a_k + 1][a_row & 63] = nav.y;
                As[nxt][a_k + 2][a_row & 63] = nav.z;
                As[nxt][a_k + 3][a_row & 63] = nav.w;
            }
            *(float4*)&Bs[nxt][b_k][b_c] = nbv;
            __syncthreads();
            cur = nxt;
        }
    }

    // epilogue: 4 rows x (two float4 column groups)
    #pragma unroll
    for (int i = 0; i < 4; i++) {
        int grr = block_m + m0 + i;
        float* c_row = C + (long long)(grr / Mchunk) * c_bs
                         + (long long)((grr % Mchunk) + c_off) * Nper + block_n;
        if (acc) {
            float4 o0 = *(float4*)(c_row + n0);
            float4 o1 = *(float4*)(c_row + n0 + 64);
            o0.x += accv[i][0]; o0.y += accv[i][1]; o0.z += accv[i][2]; o0.w += accv[i][3];
            o1.x += accv[i][4]; o1.y += accv[i][5]; o1.z += accv[i][6]; o1.w += accv[i][7];
            *(float4*)(c_row + n0)      = o0;
            *(float4*)(c_row + n0 + 64) = o1;
        } else {
            float4 o0 = {accv[i][0], accv[i][1], accv[i][2], accv[i][3]};
            float4 o1 = {accv[i][4], accv[i][5], accv[i][6], accv[i][7]};
            *(float4*)(c_row + n0)      = o0;
            *(float4*)(c_row + n0 + 64) = o1;
        }
    }
}

// ---------------- RMSNorm: one block per row, D=1024 ----------------
__global__ __launch_bounds__(256) void rmsnorm_kernel(
    const float* __restrict__ X, const float* __restrict__ W, float* __restrict__ O)
{
    int row = blockIdx.x;
    int t = threadIdx.x;
    const float4* x = (const float4*)(X + (long long)row * DD);
    float4 xv = x[t];
    float ss = xv.x*xv.x + xv.y*xv.y + xv.z*xv.z + xv.w*xv.w;
    #pragma unroll
    for (int off = 16; off >= 1; off >>= 1)
        ss += __shfl_xor_sync(0xffffffffu, ss, off);
    __shared__ float red[8];
    if ((t & 31) == 0) red[t >> 5] = ss;
    __syncthreads();
    __shared__ float s_inv;
    if (t == 0) {
        float tot = 0.f;
        #pragma unroll
        for (int i = 0; i < 8; i++) tot += red[i];
        s_inv = rsqrtf(tot * (1.0f / DD) + 1e-5f);
    }
    __syncthreads();
    float inv = s_inv;
    float4 wv = ((const float4*)W)[t];
    float4 ov = {xv.x*inv*wv.x, xv.y*inv*wv.y, xv.z*inv*wv.z, xv.w*inv*wv.w};
    ((float4*)(O + (long long)row * DD))[t] = ov;
}

// ---------------- SwiGLU: h1 = silu(h1) * h3 (in place), float4 ----------------
__global__ void silu_mul_kernel(float* __restrict__ h1, const float* __restrict__ h3, int n4)
{
    int i = blockIdx.x * blockDim.x + threadIdx.x;
    if (i >= n4) return;
    float4 a = ((float4*)h1)[i];
    float4 b = ((const float4*)h3)[i];
    a.x = a.x / (1.f + expf(-a.x)) * b.x;
    a.y = a.y / (1.f + expf(-a.y)) * b.y;
    a.z = a.z / (1.f + expf(-a.z)) * b.z;
    a.w = a.w / (1.f + expf(-a.w)) * b.w;
    ((float4*)h1)[i] = a;
}

// ---------------- RoPE (in place) on rows [l_begin, l_begin+l_count) ----------------
__global__ void rope_kernel(float* __restrict__ T, const float* __restrict__ fcos,
                            const float* __restrict__ fsin, int l_begin, int l_count)
{
    int idx = blockIdx.x * blockDim.x + threadIdx.x;
    int total = BB * l_count * HH * (HDIM / 2);
    if (idx >= total) return;
    int i = idx & 31;
    int h = (idx >> 5) & 15;
    int rest = idx >> 9;
    int lr = rest % l_count;
    int b = rest / l_count;
    int l = l_begin + lr;
    float* p = T + ((long long)b * LL + l) * DD + h * HDIM + 2 * i;
    float c = fcos[l * 32 + i];
    float s = fsin[l * 32 + i];
    float2 v = *(float2*)p;
    float2 o = {v.x * c - v.y * s, v.x * s + v.y * c};
    *(float2*)p = o;
}

// ---------------- Flash attention (fp32), q rows M..L only ----------------
__global__ __launch_bounds__(256) void attn_kernel(
    const float* __restrict__ Qg, const float* __restrict__ Kg, const float* __restrict__ Vg,
    float* __restrict__ Yg, int step)
{
    __shared__ float Qs[64][64];
    __shared__ float KP[64][64];
    __shared__ float Vs[64][64];
    int qt = blockIdx.x, h = blockIdx.y, b = blockIdx.z;
    int tid = threadIdx.x, tx = tid & 15, ty = tid >> 4;
    int r4 = ty << 2, c4 = tx << 2;

    const float* qbase = Qg + ((long long)b * LL + MM + qt * 64) * DD + h * HDIM;
    #pragma unroll
    for (int i = 0; i < 4; i++) {
        int r = (tid >> 4) + i * 16;
        int c = (tid & 15) << 2;
        *(float4*)&Qs[r][c] = *(const float4*)(qbase + (long long)r * DD + c);
    }

    float m_i[4], l_i[4], o[4][4];
    #pragma unroll
    for (int i = 0; i < 4; i++) {
        m_i[i] = -1e30f; l_i[i] = 0.f;
        #pragma unroll
        for (int j = 0; j < 4; j++) o[i][j] = 0.f;
    }

    int nkt = 9 + qt;
    for (int kt = 0; kt < nkt; kt++) {
        __syncthreads();
        const float* kbase = Kg + ((long long)b * LL + kt * 64) * DD + h * HDIM;
        const float* vbase = Vg + ((long long)b * LL + kt * 64) * DD + h * HDIM;
        #pragma unroll
        for (int i = 0; i < 4; i++) {
            int c  = tid >> 2;
            int d0 = ((tid & 3) << 2) + i * 16;
            float4 kv = *(const float4*)(kbase + (long long)c * DD + d0);
            KP[d0 + 0][c] = kv.x; KP[d0 + 1][c] = kv.y;
            KP[d0 + 2][c] = kv.z; KP[d0 + 3][c] = kv.w;
            int r = (tid >> 4) + i * 16;
            int cc = (tid & 15) << 2;
            *(float4*)&Vs[r][cc] = *(const float4*)(vbase + (long long)r * DD + cc);
        }
        __syncthreads();

        float s[4][4];
        #pragma unroll
        for (int i = 0; i < 4; i++)
            #pragma unroll
            for (int j = 0; j < 4; j++) s[i][j] = 0.f;
        #pragma unroll
        for (int d0 = 0; d0 < 64; d0 += 4) {
            float areg[4][4];
            #pragma unroll
            for (int i = 0; i < 4; i++) {
                float4 t = *(const float4*)&Qs[r4 + i][d0];
                areg[i][0] = t.x; areg[i][1] = t.y; areg[i][2] = t.z; areg[i][3] = t.w;
            }
            #pragma unroll
            for (int dd = 0; dd < 4; dd++) {
                float4 bt = *(const float4*)&KP[d0 + dd][c4];
                float br[4] = {bt.x, bt.y, bt.z, bt.w};
                #pragma unroll
                for (int i = 0; i < 4; i++)
                    #pragma unroll
                    for (int j = 0; j < 4; j++)
                        s[i][j] += areg[i][dd] * br[j];
            }
        }

        bool diag = (kt == 8 + qt);
        #pragma unroll
        for (int i = 0; i < 4; i++) {
            #pragma unroll
            for (int j = 0; j < 4; j++) {
                s[i][j] *= 0.125f;
                if (diag && (c4 + j > r4 + i)) s[i][j] = -1e30f;
            }
        }

        #pragma unroll
        for (int i = 0; i < 4; i++) {
            float tm = fmaxf(fmaxf(s[i][0], s[i][1]), fmaxf(s[i][2], s[i][3]));
            tm = fmaxf(tm, __shfl_xor_sync(0xffffffffu, tm, 8));
            tm = fmaxf(tm, __shfl_xor_sync(0xffffffffu, tm, 4));
            tm = fmaxf(tm, __shfl_xor_sync(0xffffffffu, tm, 2));
            tm = fmaxf(tm, __shfl_xor_sync(0xffffffffu, tm, 1));
            float mnew = fmaxf(m_i[i], tm);
            float alpha = expf(m_i[i] - mnew);
            float rs = 0.f;
            #pragma unroll
            for (int j = 0; j < 4; j++) {
                float p = expf(s[i][j] - mnew);
                s[i][j] = p; rs += p;
            }
            rs += __shfl_xor_sync(0xffffffffu, rs, 8);
            rs += __shfl_xor_sync(0xffffffffu, rs, 4);
            rs += __shfl_xor_sync(0xffffffffu, rs, 2);
            rs += __shfl_xor_sync(0xffffffffu, rs, 1);
            l_i[i] = l_i[i] * alpha + rs;
            m_i[i] = mnew;
            #pragma unroll
            for (int j = 0; j < 4; j++) o[i][j] *= alpha;
        }

        __syncthreads();
        #pragma unroll
        for (int i = 0; i < 4; i++) {
            float4 pv = {s[i][0], s[i][1], s[i][2], s[i][3]};
            *(float4*)&KP[r4 + i][c4] = pv;
        }
        __syncthreads();

        #pragma unroll
        for (int c0 = 0; c0 < 64; c0 += 4) {
            float preg[4][4];
            #pragma unroll
            for (int i = 0; i < 4; i++) {
                float4 t = *(const float4*)&KP[r4 + i][c0];
                preg[i][0] = t.x; preg[i][1] = t.y; preg[i][2] = t.z; preg[i][3] = t.w;
            }
            #pragma unroll
            for (int cc = 0; cc < 4; cc++) {
                float4 vt = *(const float4*)&Vs[c0 + cc][c4];
                float vr[4] = {vt.x, vt.y, vt.z, vt.w};
                #pragma unroll
                for (int i = 0; i < 4; i++)
                    #pragma unroll
                    for (int j = 0; j < 4; j++)
                        o[i][j] += preg[i][cc] * vr[j];
            }
        }
    }

    float* ybase = Yg + ((long long)b * SS + step * MM + qt * 64) * DD + h * HDIM;
    #pragma unroll
    for (int i = 0; i < 4; i++) {
        float inv = 1.f / l_i[i];
        float4 ov = {o[i][0]*inv, o[i][1]*inv, o[i][2]*inv, o[i][3]*inv};
        *(float4*)(ybase + (long long)(r4 + i) * DD + c4) = ov;
    }
}

// ---------------- host orchestration ----------------
static void launch_gemm3(const float* A,
                         const float* B0, const float* B1, const float* B2,
                         float* C0, float* C1, float* C2,
                         int nsub, int Mtot, int Nper, int K,
                         long long a_bs, int a_off, int Mchunk,
                         long long c_bs, int c_off, int acc)
{
    int nbper = Nper / BN;
    dim3 grid(nsub * nbper, Mtot / BM);
    sgemm_kernel<<<grid, 256>>>(A, B0, B1, B2, C0, C1, C2,
                                Nper, K, nbper, a_bs, a_off, Mchunk, c_bs, c_off, acc);
}

extern "C" void kernel_launch(void* const* d_in, const int* in_sizes, int n_in,
                              void* d_out, int out_size)
{
    const float* x     = (const float*)d_in[0];
    const float* fcos  = (const float*)d_in[1];
    const float* fsin  = (const float*)d_in[2];
    const float* wq    = (const float*)d_in[3];
    const float* wk    = (const float*)d_in[4];
    const float* wv    = (const float*)d_in[5];
    const float* wo    = (const float*)d_in[6];
    const float* wm    = (const float*)d_in[7];
    const float* wkm   = (const float*)d_in[8];
    const float* wvm   = (const float*)d_in[9];
    const float* w1    = (const float*)d_in[10];
    const float* w3    = (const float*)d_in[11];
    const float* w2    = (const float*)d_in[12];
    const float* ffn_w = (const float*)d_in[13];
    const float* mem_w = (const float*)d_in[14];
    const float* omem  = (const float*)d_in[15];
    float* out = (float*)d_out;

    float *Y, *Qb, *Kb, *Vb, *OM2, *HN, *H1, *H3, *OMN;
    cudaGetSymbolAddress((void**)&Y,   g_Y);
    cudaGetSymbolAddress((void**)&Qb,  g_Q);
    cudaGetSymbolAddress((void**)&Kb,  g_K);
    cudaGetSymbolAddress((void**)&Vb,  g_V);
    cudaGetSymbolAddress((void**)&OM2, g_OM2);
    cudaGetSymbolAddress((void**)&HN,  g_HN);
    cudaGetSymbolAddress((void**)&H1,  g_H1);
    cudaGetSymbolAddress((void**)&H3,  g_H3);
    cudaGetSymbolAddress((void**)&OMN, g_OMN);

    const long long XBS = (long long)SS * DD;
    const long long LBS = (long long)LL * DD;
    const long long MBS = (long long)MM * DD;

    for (int step = 0; step < NSTEP; step++) {
        // xq/xk/xv -> rows M..L of Q/K/V (merged 3-output GEMM, 384 CTAs)
        launch_gemm3(x, wq, wk, wv, Qb, Kb, Vb, 3,
                     BB*MM, DD, DD, XBS, step*MM, MM, LBS, MM, 0);

        // om @ wm  (step 0: origin_mem broadcast across batch via a_bs=0)
        if (step == 0)
            launch_gemm3(omem, wm, 0, 0, OM2, 0, 0, 1,
                         BB*MM, DD, DD, 0, 0, MM, MBS, 0, 0);
        else
            launch_gemm3(Y, wm, 0, 0, OM2, 0, 0, 1,
                         BB*MM, DD, DD, XBS, (step-1)*MM, MM, MBS, 0, 0);

        // FFN with residual into OM2
        rmsnorm_kernel<<<BB*MM, 256>>>(OM2, ffn_w, HN);
        launch_gemm3(HN, w1, w3, 0, H1, H3, 0, 2,
                     BB*MM, HID, DD, 0, 0, BB*MM, 0, 0, 0);
        {
            int n4 = BB * MM * HID / 4;
            silu_mul_kernel<<<(n4 + 255) / 256, 256>>>(H1, H3, n4);
        }
        launch_gemm3(H1, w2, 0, 0, OM2, 0, 0, 1,
                     BB*MM, DD, HID, 0, 0, BB*MM, 0, 0, 1);  // accumulate

        rmsnorm_kernel<<<BB*MM, 256>>>(OM2, mem_w, OMN);

        // mk -> K rows 0..M ; mv -> V rows 0..M (merged 2-output GEMM)
        launch_gemm3(OMN, wkm, wvm, 0, Kb, Vb, 0, 2,
                     BB*MM, DD, DD, MBS, 0, MM, LBS, 0, 0);

        // RoPE: K rows 0..L, Q rows M..L
        {
            int totK = BB * LL * HH * 32;
            rope_kernel<<<(totK + 255) / 256, 256>>>(Kb, fcos, fsin, 0, LL);
            int totQ = BB * MM * HH * 32;
            rope_kernel<<<(totQ + 255) / 256, 256>>>(Qb, fcos, fsin, MM, MM);
        }

        // attention (q rows M..L only) -> Y[:, step*M : (step+1)*M]
        attn_kernel<<<dim3(8, HH, BB), 256>>>(Qb, Kb, Vb, Y, step);
    }

    // final projection: out = Y @ wo
    launch_gemm3(Y, wo, 0, 0, out, 0, 0, 1,
                 BB*SS, DD, DD, 0, 0, BB*SS, 0, 0, 0);
}

// round 4
// speedup vs baseline: 2.3373x; 2.3373x over previous
#include <cuda_runtime.h>
#include <cuda_bf16.h>
#include <math.h>
#include <stdint.h>

// Problem constants
#define BB 2
#define SS 4096
#define DD 1024
#define HH 16
#define HDIM 64
#define MM 512
#define LL 1024          // 2*MM
#define HID 2816
#define NSTEP 8          // SS/MM

// ---------------- scratch (device globals; no allocation allowed) ----------------
__device__ float g_Y  [BB * SS * DD];
__device__ float g_Q  [BB * LL * DD];
__device__ float g_K  [BB * LL * DD];
__device__ float g_V  [BB * LL * DD];
__device__ float g_OM2[BB * MM * DD];
__device__ float g_HN [BB * MM * DD];
__device__ float g_H1 [BB * MM * HID];
__device__ float g_H3 [BB * MM * HID];
__device__ float g_OMN[BB * MM * DD];

// packed bf16 hi/lo weight tiles.
// Tile = one (n_blk 64 x k_chunk 32) block, stored n-major: 64 rows of 80 bytes
// (32 bf16 k-values + 16B pad for bank-conflict-free lds.32 fragments).
// Tile order for weight: tile = n_blk * KC + kc;  tile bytes = 5120.
#define TILE_B 5120
#define PK_SQ  (512 * 2560)            // 16 nblk * 32 kc tiles, elems
#define PK_W13 (1408 * 2560)           // 44 nblk * 32 kc
#define PK_W2  (1408 * 2560)           // 16 nblk * 88 kc
#define PK_TOTAL (7*PK_SQ + 2*PK_W13 + PK_W2)
__device__ __align__(256) __nv_bfloat16 g_pk_hi[PK_TOTAL];
__device__ __align__(256) __nv_bfloat16 g_pk_lo[PK_TOTAL];

#define OFF_WQ  0
#define OFF_WK  (1*PK_SQ)
#define OFF_WV  (2*PK_SQ)
#define OFF_WM  (3*PK_SQ)
#define OFF_WKM (4*PK_SQ)
#define OFF_WVM (5*PK_SQ)
#define OFF_WO  (6*PK_SQ)
#define OFF_W1  (7*PK_SQ)
#define OFF_W3  (7*PK_SQ + PK_W13)
#define OFF_W2  (7*PK_SQ + 2*PK_W13)

// ---------------- bf16 m16n8k16 mma (baseline PTX, legacy HMMA pipe) ----------------
__device__ __forceinline__ void mma16816(float* c, const uint32_t* a, const uint32_t* b) {
    asm volatile(
        "mma.sync.aligned.m16n8k16.row.col.f32.bf16.bf16.f32 "
        "{%0,%1,%2,%3}, {%4,%5,%6,%7}, {%8,%9}, {%0,%1,%2,%3};"
        : "+f"(c[0]), "+f"(c[1]), "+f"(c[2]), "+f"(c[3])
        : "r"(a[0]), "r"(a[1]), "r"(a[2]), "r"(a[3]), "r"(b[0]), "r"(b[1]));
}

// ================= weight repack: fp32 [K,N] -> n-major bf16 hi/lo tiles =================
__global__ __launch_bounds__(256) void repack_kernel(
    const float* __restrict__ W, __nv_bfloat16* __restrict__ Wh,
    __nv_bfloat16* __restrict__ Wl, int N)
{
    __shared__ unsigned char sh[TILE_B];
    __shared__ unsigned char sl[TILE_B];
    int kc = blockIdx.x, nb = blockIdx.y;
    int KC = gridDim.x;
    for (int e = threadIdx.x; e < 2048; e += 256) {
        int n_l = e & 63, k_l = e >> 6;
        float v = W[(long long)(kc * 32 + k_l) * N + nb * 64 + n_l];
        __nv_bfloat16 h = __float2bfloat16_rn(v);
        __nv_bfloat16 l = __float2bfloat16_rn(v - __bfloat162float(h));
        unsigned off = (unsigned)(n_l * 80 + k_l * 2);
        *(__nv_bfloat16*)(sh + off) = h;
        *(__nv_bfloat16*)(sl + off) = l;
    }
    __syncthreads();
    long long tb = ((long long)nb * KC + kc) * TILE_B;
    uint4* dh = (uint4*)((char*)Wh + tb);
    uint4* dl = (uint4*)((char*)Wl + tb);
    int t = threadIdx.x;
    dh[t] = ((uint4*)sh)[t];
    dl[t] = ((uint4*)sl)[t];
    if (t < 64) {
        dh[256 + t] = ((uint4*)sh)[256 + t];
        dl[256 + t] = ((uint4*)sl)[256 + t];
    }
}

// ================= mma.sync GEMM =================
// C[row,col] (+)= A[row,:] @ B, bf16 hi/lo split (AhBh + AhBl + AlBh, fp32 acc).
// CTA tile 128(M) x 64(N), BK=32. 256 threads = 8 warps: warp (mw = w&3, nw = w>>2),
// warp tile 32x32 = 2 m-tiles x 4 n-tiles of m16n8k16, x3 products.
// Multi-output over up to 3 B/C pairs (sel = blockIdx.x / nbper).
// Row mapping: A idx = (r/Mchunk)*a_bs + ((r%Mchunk)+a_off)*K ; C same with Nper.
#define SA_H 0
#define SA_L 10240
#define SB_H 20480
#define SB_L 25600

__global__ __launch_bounds__(256) void mma_gemm(
    const float* __restrict__ A,
    const __nv_bfloat16* __restrict__ Bh0, const __nv_bfloat16* __restrict__ Bl0,
    const __nv_bfloat16* __restrict__ Bh1, const __nv_bfloat16* __restrict__ Bl1,
    const __nv_bfloat16* __restrict__ Bh2, const __nv_bfloat16* __restrict__ Bl2,
    float* __restrict__ C0, float* __restrict__ C1, float* __restrict__ C2,
    int Nper, int K, int nbper,
    long long a_bs, int a_off, int Mchunk,
    long long c_bs, int c_off, int acc)
{
    __shared__ __align__(16) unsigned char smem[30720];

    int tid = threadIdx.x;
    int wid = tid >> 5, lane = tid & 31;
    int g = lane >> 2, q = lane & 3;
    int mw = wid & 3, nw = wid >> 2;

    int sel = blockIdx.x / nbper;
    int n_blk = blockIdx.x - sel * nbper;
    int block_n = n_blk * 64;
    int block_m = blockIdx.y * 128;
    const __nv_bfloat16* Bh = (sel == 0) ? Bh0 : ((sel == 1) ? Bh1 : Bh2);
    const __nv_bfloat16* Bl = (sel == 0) ? Bl0 : ((sel == 1) ? Bl1 : Bl2);
    float*               C  = (sel == 0) ? C0  : ((sel == 1) ? C1  : C2);

    int nk = K >> 5;   // K/32 chunks

    // ---- loader addressing ----
    // A: thread handles float4 f = tid + j*256 (j<4): row = f>>3, c4 = f&7
    const float* aptr[4];
    unsigned     asm_off[4];
    #pragma unroll
    for (int j = 0; j < 4; j++) {
        int f = tid + j * 256;
        int row = f >> 3, c4 = f & 7;
        int gr = block_m + row;
        aptr[j] = A + (long long)(gr / Mchunk) * a_bs
                    + (long long)((gr % Mchunk) + a_off) * K + c4 * 4;
        asm_off[j] = (unsigned)(row * 80 + c4 * 8);
    }
    const char* bh_src = (const char*)Bh + (long long)n_blk * nk * TILE_B;
    const char* bl_src = (const char*)Bl + (long long)n_blk * nk * TILE_B;

    float c[2][4][4];
    #pragma unroll
    for (int i = 0; i < 2; i++)
        #pragma unroll
        for (int j = 0; j < 4; j++)
            #pragma unroll
            for (int e = 0; e < 4; e++) c[i][j][e] = 0.f;

    // ---- prefetch chunk 0 ----
    float4 pa[4];
    uint4 pbh0, pbh1, pbl0, pbl1;
    #pragma unroll
    for (int j = 0; j < 4; j++) pa[j] = *(const float4*)(aptr[j]);
    pbh0 = *(const uint4*)(bh_src + tid * 16);
    pbl0 = *(const uint4*)(bl_src + tid * 16);
    if (tid < 64) {
        pbh1 = *(const uint4*)(bh_src + (256 + tid) * 16);
        pbl1 = *(const uint4*)(bl_src + (256 + tid) * 16);
    }

    for (int it = 0; it < nk; it++) {
        if (it > 0) __syncthreads();   // previous compute done before overwrite

        // ---- store prefetched chunk to smem ----
        #pragma unroll
        for (int j = 0; j < 4; j++) {
            float4 v = pa[j];
            __nv_bfloat16 hx = __float2bfloat16_rn(v.x);
            __nv_bfloat16 hy = __float2bfloat16_rn(v.y);
            __nv_bfloat16 hz = __float2bfloat16_rn(v.z);
            __nv_bfloat16 hw = __float2bfloat16_rn(v.w);
            __nv_bfloat16 lx = __float2bfloat16_rn(v.x - __bfloat162float(hx));
            __nv_bfloat16 ly = __float2bfloat16_rn(v.y - __bfloat162float(hy));
            __nv_bfloat16 lz = __float2bfloat16_rn(v.z - __bfloat162float(hz));
            __nv_bfloat16 lw = __float2bfloat16_rn(v.w - __bfloat162float(hw));
            uint2 hv, lv;
            hv.x = (uint32_t)__bfloat16_as_ushort(hx) | ((uint32_t)__bfloat16_as_ushort(hy) << 16);
            hv.y = (uint32_t)__bfloat16_as_ushort(hz) | ((uint32_t)__bfloat16_as_ushort(hw) << 16);
            lv.x = (uint32_t)__bfloat16_as_ushort(lx) | ((uint32_t)__bfloat16_as_ushort(ly) << 16);
            lv.y = (uint32_t)__bfloat16_as_ushort(lz) | ((uint32_t)__bfloat16_as_ushort(lw) << 16);
            *(uint2*)(smem + SA_H + asm_off[j]) = hv;
            *(uint2*)(smem + SA_L + asm_off[j]) = lv;
        }
        *(uint4*)(smem + SB_H + tid * 16) = pbh0;
        *(uint4*)(smem + SB_L + tid * 16) = pbl0;
        if (tid < 64) {
            *(uint4*)(smem + SB_H + (256 + tid) * 16) = pbh1;
            *(uint4*)(smem + SB_L + (256 + tid) * 16) = pbl1;
        }
        __syncthreads();

        // ---- prefetch next chunk (overlaps with mma below) ----
        if (it + 1 < nk) {
            #pragma unroll
            for (int j = 0; j < 4; j++) pa[j] = *(const float4*)(aptr[j] + (it + 1) * 32);
            long long bo = (long long)(it + 1) * TILE_B;
            pbh0 = *(const uint4*)(bh_src + bo + tid * 16);
            pbl0 = *(const uint4*)(bl_src + bo + tid * 16);
            if (tid < 64) {
                pbh1 = *(const uint4*)(bh_src + bo + (256 + tid) * 16);
                pbl1 = *(const uint4*)(bl_src + bo + (256 + tid) * 16);
            }
        }

        // ---- compute: 2 k-steps of 16 ----
        #pragma unroll
        for (int kk = 0; kk < 2; kk++) {
            int kb = kk * 32 + q * 4;       // byte offset of this thread's k-pair
            uint32_t ah[2][4], al[2][4], bh[4][2], bl[4][2];
            #pragma unroll
            for (int i = 0; i < 2; i++) {
                int r0 = (mw * 32 + i * 16 + g) * 80;
                int r1 = r0 + 8 * 80;
                ah[i][0] = *(const uint32_t*)(smem + SA_H + r0 + kb);
                ah[i][1] = *(const uint32_t*)(smem + SA_H + r1 + kb);
                ah[i][2] = *(const uint32_t*)(smem + SA_H + r0 + kb + 16);
                ah[i][3] = *(const uint32_t*)(smem + SA_H + r1 + kb + 16);
                al[i][0] = *(const uint32_t*)(smem + SA_L + r0 + kb);
                al[i][1] = *(const uint32_t*)(smem + SA_L + r1 + kb);
                al[i][2] = *(const uint32_t*)(smem + SA_L + r0 + kb + 16);
                al[i][3] = *(const uint32_t*)(smem + SA_L + r1 + kb + 16);
            }
            #pragma unroll
            for (int j = 0; j < 4; j++) {
                int nr = (nw * 32 + j * 8 + g) * 80;
                bh[j][0] = *(const uint32_t*)(smem + SB_H + nr + kb);
                bh[j][1] = *(const uint32_t*)(smem + SB_H + nr + kb + 16);
                bl[j][0] = *(const uint32_t*)(smem + SB_L + nr + kb);
                bl[j][1] = *(const uint32_t*)(smem + SB_L + nr + kb + 16);
            }
            #pragma unroll
            for (int i = 0; i < 2; i++)
                #pragma unroll
                for (int j = 0; j < 4; j++) {
                    mma16816(c[i][j], ah[i], bh[j]);
                    mma16816(c[i][j], ah[i], bl[j]);
                    mma16816(c[i][j], al[i], bh[j]);
                }
        }
    }

    // ---- epilogue ----
    #pragma unroll
    for (int i = 0; i < 2; i++) {
        int row0 = block_m + mw * 32 + i * 16 + g;
        #pragma unroll
        for (int half = 0; half < 2; half++) {
            int gr = row0 + half * 8;
            float* crow = C + (long long)(gr / Mchunk) * c_bs
                            + (long long)((gr % Mchunk) + c_off) * Nper + block_n;
            #pragma unroll
            for (int j = 0; j < 4; j++) {
                int col = nw * 32 + j * 8 + 2 * q;
                float2 v;
                v.x = c[i][j][half * 2 + 0];
                v.y = c[i][j][half * 2 + 1];
                if (acc) {
                    float2 o = *(float2*)(crow + col);
                    v.x += o.x; v.y += o.y;
                }
                *(float2*)(crow + col) = v;
            }
        }
    }
}

// ---------------- RMSNorm ----------------
__global__ __launch_bounds__(256) void rmsnorm_kernel(
    const float* __restrict__ X, const float* __restrict__ W, float* __restrict__ O)
{
    int row = blockIdx.x;
    int t = threadIdx.x;
    const float4* x = (const float4*)(X + (long long)row * DD);
    float4 xv = x[t];
    float ss = xv.x*xv.x + xv.y*xv.y + xv.z*xv.z + xv.w*xv.w;
    #pragma unroll
    for (int off = 16; off >= 1; off >>= 1)
        ss += __shfl_xor_sync(0xffffffffu, ss, off);
    __shared__ float red[8];
    if ((t & 31) == 0) red[t >> 5] = ss;
    __syncthreads();
    __shared__ float s_inv;
    if (t == 0) {
        float tot = 0.f;
        #pragma unroll
        for (int i = 0; i < 8; i++) tot += red[i];
        s_inv = rsqrtf(tot * (1.0f / DD) + 1e-5f);
    }
    __syncthreads();
    float inv = s_inv;
    float4 wv = ((const float4*)W)[t];
    float4 ov = {xv.x*inv*wv.x, xv.y*inv*wv.y, xv.z*inv*wv.z, xv.w*inv*wv.w};
    ((float4*)(O + (long long)row * DD))[t] = ov;
}

// ---------------- SwiGLU ----------------
__global__ void silu_mul_kernel(float* __restrict__ h1, const float* __restrict__ h3, int n4)
{
    int i = blockIdx.x * blockDim.x + threadIdx.x;
    if (i >= n4) return;
    float4 a = ((float4*)h1)[i];
    float4 b = ((const float4*)h3)[i];
    a.x = a.x / (1.f + expf(-a.x)) * b.x;
    a.y = a.y / (1.f + expf(-a.y)) * b.y;
    a.z = a.z / (1.f + expf(-a.z)) * b.z;
    a.w = a.w / (1.f + expf(-a.w)) * b.w;
    ((float4*)h1)[i] = a;
}

// ---------------- RoPE ----------------
__global__ void rope_kernel(float* __restrict__ T, const float* __restrict__ fcos,
                            const float* __restrict__ fsin, int l_begin, int l_count)
{
    int idx = blockIdx.x * blockDim.x + threadIdx.x;
    int total = BB * l_count * HH * (HDIM / 2);
    if (idx >= total) return;
    int i = idx & 31;
    int h = (idx >> 5) & 15;
    int rest = idx >> 9;
    int lr = rest % l_count;
    int b = rest / l_count;
    int l = l_begin + lr;
    float* p = T + ((long long)b * LL + l) * DD + h * HDIM + 2 * i;
    float c = fcos[l * 32 + i];
    float s = fsin[l * 32 + i];
    float2 v = *(float2*)p;
    float2 o = {v.x * c - v.y * s, v.x * s + v.y * c};
    *(float2*)p = o;
}

// ---------------- Flash attention (fp32), q rows M..L only ----------------
__global__ __launch_bounds__(256) void attn_kernel(
    const float* __restrict__ Qg, const float* __restrict__ Kg, const float* __restrict__ Vg,
    float* __restrict__ Yg, int step)
{
    __shared__ float Qs[64][64];
    __shared__ float KP[64][64];
    __shared__ float Vs[64][64];
    int qt = blockIdx.x, h = blockIdx.y, b = blockIdx.z;
    int tid = threadIdx.x, tx = tid & 15, ty = tid >> 4;
    int r4 = ty << 2, c4 = tx << 2;

    const float* qbase = Qg + ((long long)b * LL + MM + qt * 64) * DD + h * HDIM;
    #pragma unroll
    for (int i = 0; i < 4; i++) {
        int r = (tid >> 4) + i * 16;
        int c = (tid & 15) << 2;
        *(float4*)&Qs[r][c] = *(const float4*)(qbase + (long long)r * DD + c);
    }

    float m_i[4], l_i[4], o[4][4];
    #pragma unroll
    for (int i = 0; i < 4; i++) {
        m_i[i] = -1e30f; l_i[i] = 0.f;
        #pragma unroll
        for (int j = 0; j < 4; j++) o[i][j] = 0.f;
    }

    int nkt = 9 + qt;
    for (int kt = 0; kt < nkt; kt++) {
        __syncthreads();
        const float* kbase = Kg + ((long long)b * LL + kt * 64) * DD + h * HDIM;
        const float* vbase = Vg + ((long long)b * LL + kt * 64) * DD + h * HDIM;
        #pragma unroll
        for (int i = 0; i < 4; i++) {
            int c  = tid >> 2;
            int d0 = ((tid & 3) << 2) + i * 16;
            float4 kv = *(const float4*)(kbase + (long long)c * DD + d0);
            KP[d0 + 0][c] = kv.x; KP[d0 + 1][c] = kv.y;
            KP[d0 + 2][c] = kv.z; KP[d0 + 3][c] = kv.w;
            int r = (tid >> 4) + i * 16;
            int cc = (tid & 15) << 2;
            *(float4*)&Vs[r][cc] = *(const float4*)(vbase + (long long)r * DD + cc);
        }
        __syncthreads();

        float s[4][4];
        #pragma unroll
        for (int i = 0; i < 4; i++)
            #pragma unroll
            for (int j = 0; j < 4; j++) s[i][j] = 0.f;
        #pragma unroll
        for (int d0 = 0; d0 < 64; d0 += 4) {
            float areg[4][4];
            #pragma unroll
            for (int i = 0; i < 4; i++) {
                float4 t = *(const float4*)&Qs[r4 + i][d0];
                areg[i][0] = t.x; areg[i][1] = t.y; areg[i][2] = t.z; areg[i][3] = t.w;
            }
            #pragma unroll
            for (int dd = 0; dd < 4; dd++) {
                float4 bt = *(const float4*)&KP[d0 + dd][c4];
                float br[4] = {bt.x, bt.y, bt.z, bt.w};
                #pragma unroll
                for (int i = 0; i < 4; i++)
                    #pragma unroll
                    for (int j = 0; j < 4; j++)
                        s[i][j] += areg[i][dd] * br[j];
            }
        }

        bool diag = (kt == 8 + qt);
        #pragma unroll
        for (int i = 0; i < 4; i++) {
            #pragma unroll
            for (int j = 0; j < 4; j++) {
                s[i][j] *= 0.125f;
                if (diag && (c4 + j > r4 + i)) s[i][j] = -1e30f;
            }
        }

        #pragma unroll
        for (int i = 0; i < 4; i++) {
            float tm = fmaxf(fmaxf(s[i][0], s[i][1]), fmaxf(s[i][2], s[i][3]));
            tm = fmaxf(tm, __shfl_xor_sync(0xffffffffu, tm, 8));
            tm = fmaxf(tm, __shfl_xor_sync(0xffffffffu, tm, 4));
            tm = fmaxf(tm, __shfl_xor_sync(0xffffffffu, tm, 2));
            tm = fmaxf(tm, __shfl_xor_sync(0xffffffffu, tm, 1));
            float mnew = fmaxf(m_i[i], tm);
            float alpha = expf(m_i[i] - mnew);
            float rs = 0.f;
            #pragma unroll
            for (int j = 0; j < 4; j++) {
                float p = expf(s[i][j] - mnew);
                s[i][j] = p; rs += p;
            }
            rs += __shfl_xor_sync(0xffffffffu, rs, 8);
            rs += __shfl_xor_sync(0xffffffffu, rs, 4);
            rs += __shfl_xor_sync(0xffffffffu, rs, 2);
            rs += __shfl_xor_sync(0xffffffffu, rs, 1);
            l_i[i] = l_i[i] * alpha + rs;
            m_i[i] = mnew;
            #pragma unroll
            for (int j = 0; j < 4; j++) o[i][j] *= alpha;
        }

        __syncthreads();
        #pragma unroll
        for (int i = 0; i < 4; i++) {
            float4 pv = {s[i][0], s[i][1], s[i][2], s[i][3]};
            *(float4*)&KP[r4 + i][c4] = pv;
        }
        __syncthreads();

        #pragma unroll
        for (int c0 = 0; c0 < 64; c0 += 4) {
            float preg[4][4];
            #pragma unroll
            for (int i = 0; i < 4; i++) {
                float4 t = *(const float4*)&KP[r4 + i][c0];
                preg[i][0] = t.x; preg[i][1] = t.y; preg[i][2] = t.z; preg[i][3] = t.w;
            }
            #pragma unroll
            for (int cc = 0; cc < 4; cc++) {
                float4 vt = *(const float4*)&Vs[c0 + cc][c4];
                float vr[4] = {vt.x, vt.y, vt.z, vt.w};
                #pragma unroll
                for (int i = 0; i < 4; i++)
                    #pragma unroll
                    for (int j = 0; j < 4; j++)
                        o[i][j] += preg[i][cc] * vr[j];
            }
        }
    }

    float* ybase = Yg + ((long long)b * SS + step * MM + qt * 64) * DD + h * HDIM;
    #pragma unroll
    for (int i = 0; i < 4; i++) {
        float inv = 1.f / l_i[i];
        float4 ov = {o[i][0]*inv, o[i][1]*inv, o[i][2]*inv, o[i][3]*inv};
        *(float4*)(ybase + (long long)(r4 + i) * DD + c4) = ov;
    }
}

// ---------------- host orchestration ----------------
static void launch_tc(const float* A,
                      const __nv_bfloat16* h0, const __nv_bfloat16* l0,
                      const __nv_bfloat16* h1, const __nv_bfloat16* l1,
                      const __nv_bfloat16* h2, const __nv_bfloat16* l2,
                      float* C0, float* C1, float* C2,
                      int nsub, int Mtot, int Nper, int K,
                      long long a_bs, int a_off, int Mchunk,
                      long long c_bs, int c_off, int acc)
{
    int nbper = Nper / 64;
    dim3 grid(nsub * nbper, Mtot / 128);
    mma_gemm<<<grid, 256>>>(A, h0, l0, h1, l1, h2, l2, C0, C1, C2,
                            Nper, K, nbper, a_bs, a_off, Mchunk, c_bs, c_off, acc);
}

extern "C" void kernel_launch(void* const* d_in, const int* in_sizes, int n_in,
                              void* d_out, int out_size)
{
    const float* x     = (const float*)d_in[0];
    const float* fcos  = (const float*)d_in[1];
    const float* fsin  = (const float*)d_in[2];
    const float* wq    = (const float*)d_in[3];
    const float* wk    = (const float*)d_in[4];
    const float* wv    = (const float*)d_in[5];
    const float* wo    = (const float*)d_in[6];
    const float* wm    = (const float*)d_in[7];
    const float* wkm   = (const float*)d_in[8];
    const float* wvm   = (const float*)d_in[9];
    const float* w1    = (const float*)d_in[10];
    const float* w3    = (const float*)d_in[11];
    const float* w2    = (const float*)d_in[12];
    const float* ffn_w = (const float*)d_in[13];
    const float* mem_w = (const float*)d_in[14];
    const float* omem  = (const float*)d_in[15];
    float* out = (float*)d_out;

    float *Y, *Qb, *Kb, *Vb, *OM2, *HN, *H1, *H3, *OMN;
    __nv_bfloat16 *PH, *PL;
    cudaGetSymbolAddress((void**)&Y,   g_Y);
    cudaGetSymbolAddress((void**)&Qb,  g_Q);
    cudaGetSymbolAddress((void**)&Kb,  g_K);
    cudaGetSymbolAddress((void**)&Vb,  g_V);
    cudaGetSymbolAddress((void**)&OM2, g_OM2);
    cudaGetSymbolAddress((void**)&HN,  g_HN);
    cudaGetSymbolAddress((void**)&H1,  g_H1);
    cudaGetSymbolAddress((void**)&H3,  g_H3);
    cudaGetSymbolAddress((void**)&OMN, g_OMN);
    cudaGetSymbolAddress((void**)&PH,  g_pk_hi);
    cudaGetSymbolAddress((void**)&PL,  g_pk_lo);

    // repack all weights into n-major bf16 hi/lo tiles
    repack_kernel<<<dim3(32, 16), 256>>>(wq,  PH + OFF_WQ,  PL + OFF_WQ,  DD);
    repack_kernel<<<dim3(32, 16), 256>>>(wk,  PH + OFF_WK,  PL + OFF_WK,  DD);
    repack_kernel<<<dim3(32, 16), 256>>>(wv,  PH + OFF_WV,  PL + OFF_WV,  DD);
    repack_kernel<<<dim3(32, 16), 256>>>(wm,  PH + OFF_WM,  PL + OFF_WM,  DD);
    repack_kernel<<<dim3(32, 16), 256>>>(wkm, PH + OFF_WKM, PL + OFF_WKM, DD);
    repack_kernel<<<dim3(32, 16), 256>>>(wvm, PH + OFF_WVM, PL + OFF_WVM, DD);
    repack_kernel<<<dim3(32, 16), 256>>>(wo,  PH + OFF_WO,  PL + OFF_WO,  DD);
    repack_kernel<<<dim3(32, 44), 256>>>(w1,  PH + OFF_W1,  PL + OFF_W1,  HID);
    repack_kernel<<<dim3(32, 44), 256>>>(w3,  PH + OFF_W3,  PL + OFF_W3,  HID);
    repack_kernel<<<dim3(88, 16), 256>>>(w2,  PH + OFF_W2,  PL + OFF_W2,  DD);

    const long long XBS = (long long)SS * DD;
    const long long LBS = (long long)LL * DD;
    const long long MBS = (long long)MM * DD;

    for (int step = 0; step < NSTEP; step++) {
        // xq/xk/xv -> rows M..L of Q/K/V (fused 3-output GEMM)
        launch_tc(x, PH+OFF_WQ, PL+OFF_WQ, PH+OFF_WK, PL+OFF_WK, PH+OFF_WV, PL+OFF_WV,
                  Qb, Kb, Vb, 3, BB*MM, DD, DD, XBS, step*MM, MM, LBS, MM, 0);

        // om @ wm  (step 0: origin_mem broadcast via a_bs=0)
        if (step == 0)
            launch_tc(omem, PH+OFF_WM, PL+OFF_WM, 0,0, 0,0, OM2, 0, 0, 1,
                      BB*MM, DD, DD, 0, 0, MM, MBS, 0, 0);
        else
            launch_tc(Y, PH+OFF_WM, PL+OFF_WM, 0,0, 0,0, OM2, 0, 0, 1,
                      BB*MM, DD, DD, XBS, (step-1)*MM, MM, MBS, 0, 0);

        // FFN with residual into OM2
        rmsnorm_kernel<<<BB*MM, 256>>>(OM2, ffn_w, HN);
        launch_tc(HN, PH+OFF_W1, PL+OFF_W1, PH+OFF_W3, PL+OFF_W3, 0,0,
                  H1, H3, 0, 2, BB*MM, HID, DD, 0, 0, BB*MM, 0, 0, 0);
        {
            int n4 = BB * MM * HID / 4;
            silu_mul_kernel<<<(n4 + 255) / 256, 256>>>(H1, H3, n4);
        }
        launch_tc(H1, PH+OFF_W2, PL+OFF_W2, 0,0, 0,0, OM2, 0, 0, 1,
                  BB*MM, DD, HID, 0, 0, BB*MM, 0, 0, 1);  // accumulate

        rmsnorm_kernel<<<BB*MM, 256>>>(OM2, mem_w, OMN);

        // mk -> K rows 0..M ; mv -> V rows 0..M
        launch_tc(OMN, PH+OFF_WKM, PL+OFF_WKM, PH+OFF_WVM, PL+OFF_WVM, 0,0,
                  Kb, Vb, 0, 2, BB*MM, DD, DD, MBS, 0, MM, LBS, 0, 0);

        // RoPE: K rows 0..L, Q rows M..L
        {
            int totK = BB * LL * HH * 32;
            rope_kernel<<<(totK + 255) / 256, 256>>>(Kb, fcos, fsin, 0, LL);
            int totQ = BB * MM * HH * 32;
            rope_kernel<<<(totQ + 255) / 256, 256>>>(Qb, fcos, fsin, MM, MM);
        }

        // attention (q rows M..L only) -> Y[:, step*M : (step+1)*M]
        attn_kernel<<<dim3(8, HH, BB), 256>>>(Qb, Kb, Vb, Y, step);
    }

    // final projection: out = Y @ wo
    launch_tc(Y, PH+OFF_WO, PL+OFF_WO, 0,0, 0,0, out, 0, 0, 1,
              BB*SS, DD, DD, 0, 0, BB*SS, 0, 0, 0);
}

// round 5
// speedup vs baseline: 2.5119x; 1.0747x over previous
#include <cuda_runtime.h>
#include <cuda_bf16.h>
#include <math.h>
#include <stdint.h>

// Problem constants
#define BB 2
#define SS 4096
#define DD 1024
#define HH 16
#define HDIM 64
#define MM 512
#define LL 1024          // 2*MM
#define HID 2816
#define NSTEP 8          // SS/MM

// ---------------- scratch (device globals; no allocation allowed) ----------------
__device__ float g_Y  [BB * SS * DD];
__device__ float g_Q  [BB * LL * DD];
__device__ float g_K  [BB * LL * DD];
__device__ float g_V  [BB * LL * DD];
__device__ float g_OM2[BB * MM * DD];
__device__ float g_HN [BB * MM * DD];
__device__ float g_H1 [BB * MM * HID];
__device__ float g_H3 [BB * MM * HID];
__device__ float g_OMN[BB * MM * DD];

// packed bf16 hi/lo weight tiles.
// Tile = one (n_blk 64 x k_chunk 32) block, stored n-major: 64 rows of 80 bytes
// (32 bf16 k-values + 16B pad). Tile order: tile = n_blk * KC + kc; 5120 B each.
#define TILE_B 5120
#define PK_SQ  (512 * 2560)
#define PK_W13 (1408 * 2560)
#define PK_W2  (1408 * 2560)
#define PK_TOTAL (7*PK_SQ + 2*PK_W13 + PK_W2)
__device__ __align__(256) __nv_bfloat16 g_pk_hi[PK_TOTAL];
__device__ __align__(256) __nv_bfloat16 g_pk_lo[PK_TOTAL];

#define OFF_WQ  0
#define OFF_WK  (1*PK_SQ)
#define OFF_WV  (2*PK_SQ)
#define OFF_WM  (3*PK_SQ)
#define OFF_WKM (4*PK_SQ)
#define OFF_WVM (5*PK_SQ)
#define OFF_WO  (6*PK_SQ)
#define OFF_W1  (7*PK_SQ)
#define OFF_W3  (7*PK_SQ + PK_W13)
#define OFF_W2  (7*PK_SQ + 2*PK_W13)

// ---------------- bf16 m16n8k16 mma (baseline PTX, legacy HMMA pipe) ----------------
__device__ __forceinline__ void mma16816(float* c, const uint32_t* a, const uint32_t* b) {
    asm volatile(
        "mma.sync.aligned.m16n8k16.row.col.f32.bf16.bf16.f32 "
        "{%0,%1,%2,%3}, {%4,%5,%6,%7}, {%8,%9}, {%0,%1,%2,%3};"
        : "+f"(c[0]), "+f"(c[1]), "+f"(c[2]), "+f"(c[3])
        : "r"(a[0]), "r"(a[1]), "r"(a[2]), "r"(a[3]), "r"(b[0]), "r"(b[1]));
}

__device__ __forceinline__ void splitpack(float x, float y, uint32_t& hi, uint32_t& lo) {
    __nv_bfloat16 hx = __float2bfloat16_rn(x);
    __nv_bfloat16 hy = __float2bfloat16_rn(y);
    __nv_bfloat16 lx = __float2bfloat16_rn(x - __bfloat162float(hx));
    __nv_bfloat16 ly = __float2bfloat16_rn(y - __bfloat162float(hy));
    hi = (uint32_t)__bfloat16_as_ushort(hx) | ((uint32_t)__bfloat16_as_ushort(hy) << 16);
    lo = (uint32_t)__bfloat16_as_ushort(lx) | ((uint32_t)__bfloat16_as_ushort(ly) << 16);
}

// ================= weight repack: fp32 [K,N] -> n-major bf16 hi/lo tiles =================
__global__ __launch_bounds__(256) void repack_kernel(
    const float* __restrict__ W, __nv_bfloat16* __restrict__ Wh,
    __nv_bfloat16* __restrict__ Wl, int N)
{
    __shared__ unsigned char sh[TILE_B];
    __shared__ unsigned char sl[TILE_B];
    int kc = blockIdx.x, nb = blockIdx.y;
    int KC = gridDim.x;
    for (int e = threadIdx.x; e < 2048; e += 256) {
        int n_l = e & 63, k_l = e >> 6;
        float v = W[(long long)(kc * 32 + k_l) * N + nb * 64 + n_l];
        __nv_bfloat16 h = __float2bfloat16_rn(v);
        __nv_bfloat16 l = __float2bfloat16_rn(v - __bfloat162float(h));
        unsigned off = (unsigned)(n_l * 80 + k_l * 2);
        *(__nv_bfloat16*)(sh + off) = h;
        *(__nv_bfloat16*)(sl + off) = l;
    }
    __syncthreads();
    long long tb = ((long long)nb * KC + kc) * TILE_B;
    uint4* dh = (uint4*)((char*)Wh + tb);
    uint4* dl = (uint4*)((char*)Wl + tb);
    int t = threadIdx.x;
    dh[t] = ((uint4*)sh)[t];
    dl[t] = ((uint4*)sl)[t];
    if (t < 64) {
        dh[256 + t] = ((uint4*)sh)[256 + t];
        dl[256 + t] = ((uint4*)sl)[256 + t];
    }
}

// ================= mma.sync GEMM (unchanged from R4 — verified) =================
#define SA_H 0
#define SA_L 10240
#define SB_H 20480
#define SB_L 25600

__global__ __launch_bounds__(256) void mma_gemm(
    const float* __restrict__ A,
    const __nv_bfloat16* __restrict__ Bh0, const __nv_bfloat16* __restrict__ Bl0,
    const __nv_bfloat16* __restrict__ Bh1, const __nv_bfloat16* __restrict__ Bl1,
    const __nv_bfloat16* __restrict__ Bh2, const __nv_bfloat16* __restrict__ Bl2,
    float* __restrict__ C0, float* __restrict__ C1, float* __restrict__ C2,
    int Nper, int K, int nbper,
    long long a_bs, int a_off, int Mchunk,
    long long c_bs, int c_off, int acc)
{
    __shared__ __align__(16) unsigned char smem[30720];

    int tid = threadIdx.x;
    int wid = tid >> 5, lane = tid & 31;
    int g = lane >> 2, q = lane & 3;
    int mw = wid & 3, nw = wid >> 2;

    int sel = blockIdx.x / nbper;
    int n_blk = blockIdx.x - sel * nbper;
    int block_n = n_blk * 64;
    int block_m = blockIdx.y * 128;
    const __nv_bfloat16* Bh = (sel == 0) ? Bh0 : ((sel == 1) ? Bh1 : Bh2);
    const __nv_bfloat16* Bl = (sel == 0) ? Bl0 : ((sel == 1) ? Bl1 : Bl2);
    float*               C  = (sel == 0) ? C0  : ((sel == 1) ? C1  : C2);

    int nk = K >> 5;

    const float* aptr[4];
    unsigned     asm_off[4];
    #pragma unroll
    for (int j = 0; j < 4; j++) {
        int f = tid + j * 256;
        int row = f >> 3, c4 = f & 7;
        int gr = block_m + row;
        aptr[j] = A + (long long)(gr / Mchunk) * a_bs
                    + (long long)((gr % Mchunk) + a_off) * K + c4 * 4;
        asm_off[j] = (unsigned)(row * 80 + c4 * 8);
    }
    const char* bh_src = (const char*)Bh + (long long)n_blk * nk * TILE_B;
    const char* bl_src = (const char*)Bl + (long long)n_blk * nk * TILE_B;

    float c[2][4][4];
    #pragma unroll
    for (int i = 0; i < 2; i++)
        #pragma unroll
        for (int j = 0; j < 4; j++)
            #pragma unroll
            for (int e = 0; e < 4; e++) c[i][j][e] = 0.f;

    float4 pa[4];
    uint4 pbh0, pbh1, pbl0, pbl1;
    #pragma unroll
    for (int j = 0; j < 4; j++) pa[j] = *(const float4*)(aptr[j]);
    pbh0 = *(const uint4*)(bh_src + tid * 16);
    pbl0 = *(const uint4*)(bl_src + tid * 16);
    if (tid < 64) {
        pbh1 = *(const uint4*)(bh_src + (256 + tid) * 16);
        pbl1 = *(const uint4*)(bl_src + (256 + tid) * 16);
    }

    for (int it = 0; it < nk; it++) {
        if (it > 0) __syncthreads();

        #pragma unroll
        for (int j = 0; j < 4; j++) {
            float4 v = pa[j];
            uint2 hv, lv;
            splitpack(v.x, v.y, hv.x, lv.x);
            splitpack(v.z, v.w, hv.y, lv.y);
            *(uint2*)(smem + SA_H + asm_off[j]) = hv;
            *(uint2*)(smem + SA_L + asm_off[j]) = lv;
        }
        *(uint4*)(smem + SB_H + tid * 16) = pbh0;
        *(uint4*)(smem + SB_L + tid * 16) = pbl0;
        if (tid < 64) {
            *(uint4*)(smem + SB_H + (256 + tid) * 16) = pbh1;
            *(uint4*)(smem + SB_L + (256 + tid) * 16) = pbl1;
        }
        __syncthreads();

        if (it + 1 < nk) {
            #pragma unroll
            for (int j = 0; j < 4; j++) pa[j] = *(const float4*)(aptr[j] + (it + 1) * 32);
            long long bo = (long long)(it + 1) * TILE_B;
            pbh0 = *(const uint4*)(bh_src + bo + tid * 16);
            pbl0 = *(const uint4*)(bl_src + bo + tid * 16);
            if (tid < 64) {
                pbh1 = *(const uint4*)(bh_src + bo + (256 + tid) * 16);
                pbl1 = *(const uint4*)(bl_src + bo + (256 + tid) * 16);
            }
        }

        #pragma unroll
        for (int kk = 0; kk < 2; kk++) {
            int kb = kk * 32 + q * 4;
            uint32_t ah[2][4], al[2][4], bh[4][2], bl[4][2];
            #pragma unroll
            for (int i = 0; i < 2; i++) {
                int r0 = (mw * 32 + i * 16 + g) * 80;
                int r1 = r0 + 8 * 80;
                ah[i][0] = *(const uint32_t*)(smem + SA_H + r0 + kb);
                ah[i][1] = *(const uint32_t*)(smem + SA_H + r1 + kb);
                ah[i][2] = *(const uint32_t*)(smem + SA_H + r0 + kb + 16);
                ah[i][3] = *(const uint32_t*)(smem + SA_H + r1 + kb + 16);
                al[i][0] = *(const uint32_t*)(smem + SA_L + r0 + kb);
                al[i][1] = *(const uint32_t*)(smem + SA_L + r1 + kb);
                al[i][2] = *(const uint32_t*)(smem + SA_L + r0 + kb + 16);
                al[i][3] = *(const uint32_t*)(smem + SA_L + r1 + kb + 16);
            }
            #pragma unroll
            for (int j = 0; j < 4; j++) {
                int nr = (nw * 32 + j * 8 + g) * 80;
                bh[j][0] = *(const uint32_t*)(smem + SB_H + nr + kb);
                bh[j][1] = *(const uint32_t*)(smem + SB_H + nr + kb + 16);
                bl[j][0] = *(const uint32_t*)(smem + SB_L + nr + kb);
                bl[j][1] = *(const uint32_t*)(smem + SB_L + nr + kb + 16);
            }
            #pragma unroll
            for (int i = 0; i < 2; i++)
                #pragma unroll
                for (int j = 0; j < 4; j++) {
                    mma16816(c[i][j], ah[i], bh[j]);
                    mma16816(c[i][j], ah[i], bl[j]);
                    mma16816(c[i][j], al[i], bh[j]);
                }
        }
    }

    #pragma unroll
    for (int i = 0; i < 2; i++) {
        int row0 = block_m + mw * 32 + i * 16 + g;
        #pragma unroll
        for (int half = 0; half < 2; half++) {
            int gr = row0 + half * 8;
            float* crow = C + (long long)(gr / Mchunk) * c_bs
                            + (long long)((gr % Mchunk) + c_off) * Nper + block_n;
            #pragma unroll
            for (int j = 0; j < 4; j++) {
                int col = nw * 32 + j * 8 + 2 * q;
                float2 v;
                v.x = c[i][j][half * 2 + 0];
                v.y = c[i][j][half * 2 + 1];
                if (acc) {
                    float2 o = *(float2*)(crow + col);
                    v.x += o.x; v.y += o.y;
                }
                *(float2*)(crow + col) = v;
            }
        }
    }
}

// ---------------- RMSNorm ----------------
__global__ __launch_bounds__(256) void rmsnorm_kernel(
    const float* __restrict__ X, const float* __restrict__ W, float* __restrict__ O)
{
    int row = blockIdx.x;
    int t = threadIdx.x;
    const float4* x = (const float4*)(X + (long long)row * DD);
    float4 xv = x[t];
    float ss = xv.x*xv.x + xv.y*xv.y + xv.z*xv.z + xv.w*xv.w;
    #pragma unroll
    for (int off = 16; off >= 1; off >>= 1)
        ss += __shfl_xor_sync(0xffffffffu, ss, off);
    __shared__ float red[8];
    if ((t & 31) == 0) red[t >> 5] = ss;
    __syncthreads();
    __shared__ float s_inv;
    if (t == 0) {
        float tot = 0.f;
        #pragma unroll
        for (int i = 0; i < 8; i++) tot += red[i];
        s_inv = rsqrtf(tot * (1.0f / DD) + 1e-5f);
    }
    __syncthreads();
    float inv = s_inv;
    float4 wv = ((const float4*)W)[t];
    float4 ov = {xv.x*inv*wv.x, xv.y*inv*wv.y, xv.z*inv*wv.z, xv.w*inv*wv.w};
    ((float4*)(O + (long long)row * DD))[t] = ov;
}

// ---------------- SwiGLU ----------------
__global__ void silu_mul_kernel(float* __restrict__ h1, const float* __restrict__ h3, int n4)
{
    int i = blockIdx.x * blockDim.x + threadIdx.x;
    if (i >= n4) return;
    float4 a = ((float4*)h1)[i];
    float4 b = ((const float4*)h3)[i];
    a.x = a.x / (1.f + expf(-a.x)) * b.x;
    a.y = a.y / (1.f + expf(-a.y)) * b.y;
    a.z = a.z / (1.f + expf(-a.z)) * b.z;
    a.w = a.w / (1.f + expf(-a.w)) * b.w;
    ((float4*)h1)[i] = a;
}

// ---------------- RoPE ----------------
__global__ void rope_kernel(float* __restrict__ T, const float* __restrict__ fcos,
                            const float* __restrict__ fsin, int l_begin, int l_count)
{
    int idx = blockIdx.x * blockDim.x + threadIdx.x;
    int total = BB * l_count * HH * (HDIM / 2);
    if (idx >= total) return;
    int i = idx & 31;
    int h = (idx >> 5) & 15;
    int rest = idx >> 9;
    int lr = rest % l_count;
    int b = rest / l_count;
    int l = l_begin + lr;
    float* p = T + ((long long)b * LL + l) * DD + h * HDIM + 2 * i;
    float c = fcos[l * 32 + i];
    float s = fsin[l * 32 + i];
    float2 v = *(float2*)p;
    float2 o = {v.x * c - v.y * s, v.x * s + v.y * c};
    *(float2*)p = o;
}

// ---------------- Flash attention, tensor-core (mma.sync bf16 hi/lo) ----------------
// grid (8 qt, 16 h, 2 b), 128 threads = 4 warps; warp w owns q-rows w*16..w*16+15.
// smem: K hi/lo + V^T hi/lo, 64 rows x 144B stride (bank = 4g+q, conflict-free).
// Q (scaled by 1/8) hi/lo kept in registers (frags loaded once via smem staging).
#define AKH 0
#define AKL 9216
#define AVH 18432
#define AVL 27648

__global__ __launch_bounds__(128) void attn_mma(
    const float* __restrict__ Qg, const float* __restrict__ Kg, const float* __restrict__ Vg,
    float* __restrict__ Yg, int step)
{
    __shared__ __align__(16) unsigned char sm[36864];

    int qt = blockIdx.x, h = blockIdx.y, b = blockIdx.z;
    int tid = threadIdx.x;
    int w = tid >> 5, lane = tid & 31;
    int g = lane >> 2, q = lane & 3;
    int m0 = w << 4;

    int r  = tid >> 1;            // 0..63 (row/key handled by this thread pair)
    int ch = (tid & 1) << 5;      // 0 or 32 (column half)

    // ---- stage Q (scaled) into K region, lift fragments to registers ----
    {
        const float* src = Qg + ((long long)b * LL + MM + qt * 64 + r) * DD + h * HDIM + ch;
        #pragma unroll
        for (int i = 0; i < 8; i++) {
            float4 v = *(const float4*)(src + i * 4);
            v.x *= 0.125f; v.y *= 0.125f; v.z *= 0.125f; v.w *= 0.125f;
            uint2 hv, lv;
            splitpack(v.x, v.y, hv.x, lv.x);
            splitpack(v.z, v.w, hv.y, lv.y);
            unsigned off = (unsigned)(r * 144 + (ch + i * 4) * 2);
            *(uint2*)(sm + AKH + off) = hv;
            *(uint2*)(sm + AKL + off) = lv;
        }
    }
    __syncthreads();
    uint32_t qh[4][4], ql[4][4];
    #pragma unroll
    for (int ks = 0; ks < 4; ks++) {
        int kb = ks * 32 + q * 4;
        int r0 = (m0 + g) * 144 + kb, r1 = r0 + 8 * 144;
        qh[ks][0] = *(const uint32_t*)(sm + AKH + r0);
        qh[ks][1] = *(const uint32_t*)(sm + AKH + r1);
        qh[ks][2] = *(const uint32_t*)(sm + AKH + r0 + 16);
        qh[ks][3] = *(const uint32_t*)(sm + AKH + r1 + 16);
        ql[ks][0] = *(const uint32_t*)(sm + AKL + r0);
        ql[ks][1] = *(const uint32_t*)(sm + AKL + r1);
        ql[ks][2] = *(const uint32_t*)(sm + AKL + r0 + 16);
        ql[ks][3] = *(const uint32_t*)(sm + AKL + r1 + 16);
    }

    float m_i[2] = {-1e30f, -1e30f}, l_i[2] = {0.f, 0.f};
    float o[8][4];
    #pragma unroll
    for (int j = 0; j < 8; j++)
        #pragma unroll
        for (int e = 0; e < 4; e++) o[j][e] = 0.f;

    int nkt = 9 + qt;
    for (int kt = 0; kt < nkt; kt++) {
        __syncthreads();   // protects Q-frag reads (kt=0) and previous iteration's mma reads

        // load K tile -> KH/KL (row-major), V tile -> VH/VL (transposed)
        const float* ksrc = Kg + ((long long)b * LL + kt * 64 + r) * DD + h * HDIM + ch;
        const float* vsrc = Vg + ((long long)b * LL + kt * 64 + r) * DD + h * HDIM + ch;
        #pragma unroll
        for (int i = 0; i < 8; i++) {
            float4 kv = *(const float4*)(ksrc + i * 4);
            uint2 hv, lv;
            splitpack(kv.x, kv.y, hv.x, lv.x);
            splitpack(kv.z, kv.w, hv.y, lv.y);
            unsigned off = (unsigned)(r * 144 + (ch + i * 4) * 2);
            *(uint2*)(sm + AKH + off) = hv;
            *(uint2*)(sm + AKL + off) = lv;

            float4 vv = *(const float4*)(vsrc + i * 4);
            float ve[4] = {vv.x, vv.y, vv.z, vv.w};
            #pragma unroll
            for (int e = 0; e < 4; e++) {
                int d = ch + i * 4 + e;
                __nv_bfloat16 hh = __float2bfloat16_rn(ve[e]);
                __nv_bfloat16 llv = __float2bfloat16_rn(ve[e] - __bfloat162float(hh));
                *(__nv_bfloat16*)(sm + AVH + d * 144 + r * 2) = hh;
                *(__nv_bfloat16*)(sm + AVL + d * 144 + r * 2) = llv;
            }
        }
        __syncthreads();

        // ---- S = Q K^T (scaled) ----
        float s[8][4];
        #pragma unroll
        for (int j = 0; j < 8; j++)
            #pragma unroll
            for (int e = 0; e < 4; e++) s[j][e] = 0.f;

        #pragma unroll
        for (int ks = 0; ks < 4; ks++) {
            int kb = ks * 32 + q * 4;
            #pragma unroll
            for (int j = 0; j < 8; j++) {
                int nr = (j * 8 + g) * 144 + kb;
                uint32_t bh[2], bl[2];
                bh[0] = *(const uint32_t*)(sm + AKH + nr);
                bh[1] = *(const uint32_t*)(sm + AKH + nr + 16);
                bl[0] = *(const uint32_t*)(sm + AKL + nr);
                bl[1] = *(const uint32_t*)(sm + AKL + nr + 16);
                mma16816(s[j], qh[ks], bh);
                mma16816(s[j], qh[ks], bl);
                mma16816(s[j], ql[ks], bh);
            }
        }

        // causal mask on diagonal tile
        if (kt == nkt - 1) {
            #pragma unroll
            for (int j = 0; j < 8; j++)
                #pragma unroll
                for (int e = 0; e < 4; e++) {
                    int col = j * 8 + 2 * q + (e & 1);
                    int row = m0 + g + ((e >> 1) << 3);
                    if (col > row) s[j][e] = -1e30f;
                }
        }

        // ---- online softmax (rows g and g+8) ----
        float mx0 = -1e30f, mx1 = -1e30f;
        #pragma unroll
        for (int j = 0; j < 8; j++) {
            mx0 = fmaxf(mx0, fmaxf(s[j][0], s[j][1]));
            mx1 = fmaxf(mx1, fmaxf(s[j][2], s[j][3]));
        }
        mx0 = fmaxf(mx0, __shfl_xor_sync(0xffffffffu, mx0, 1));
        mx0 = fmaxf(mx0, __shfl_xor_sync(0xffffffffu, mx0, 2));
        mx1 = fmaxf(mx1, __shfl_xor_sync(0xffffffffu, mx1, 1));
        mx1 = fmaxf(mx1, __shfl_xor_sync(0xffffffffu, mx1, 2));
        float mn0 = fmaxf(m_i[0], mx0), mn1 = fmaxf(m_i[1], mx1);
        float al0 = expf(m_i[0] - mn0), al1 = expf(m_i[1] - mn1);
        float sum0 = 0.f, sum1 = 0.f;
        #pragma unroll
        for (int j = 0; j < 8; j++) {
            s[j][0] = expf(s[j][0] - mn0);
            s[j][1] = expf(s[j][1] - mn0);
            s[j][2] = expf(s[j][2] - mn1);
            s[j][3] = expf(s[j][3] - mn1);
            sum0 += s[j][0] + s[j][1];
            sum1 += s[j][2] + s[j][3];
        }
        sum0 += __shfl_xor_sync(0xffffffffu, sum0, 1);
        sum0 += __shfl_xor_sync(0xffffffffu, sum0, 2);
        sum1 += __shfl_xor_sync(0xffffffffu, sum1, 1);
        sum1 += __shfl_xor_sync(0xffffffffu, sum1, 2);
        l_i[0] = l_i[0] * al0 + sum0;  m_i[0] = mn0;
        l_i[1] = l_i[1] * al1 + sum1;  m_i[1] = mn1;
        #pragma unroll
        for (int j = 0; j < 8; j++) {
            o[j][0] *= al0; o[j][1] *= al0;
            o[j][2] *= al1; o[j][3] *= al1;
        }

        // ---- O += P V  (P packed from S fragments, hi/lo split) ----
        #pragma unroll
        for (int ks = 0; ks < 4; ks++) {
            uint32_t pah[4], pal[4];
            splitpack(s[2*ks][0],   s[2*ks][1],   pah[0], pal[0]);
            splitpack(s[2*ks][2],   s[2*ks][3],   pah[1], pal[1]);
            splitpack(s[2*ks+1][0], s[2*ks+1][1], pah[2], pal[2]);
            splitpack(s[2*ks+1][2], s[2*ks+1][3], pah[3], pal[3]);
            int kb = ks * 32 + q * 4;
            #pragma unroll
            for (int j = 0; j < 8; j++) {
                int nr = (j * 8 + g) * 144 + kb;
                uint32_t bh[2], bl[2];
                bh[0] = *(const uint32_t*)(sm + AVH + nr);
                bh[1] = *(const uint32_t*)(sm + AVH + nr + 16);
                bl[0] = *(const uint32_t*)(sm + AVL + nr);
                bl[1] = *(const uint32_t*)(sm + AVL + nr + 16);
                mma16816(o[j], pah, bh);
                mma16816(o[j], pah, bl);
                mma16816(o[j], pal, bh);
            }
        }
    }

    // ---- write normalized output ----
    float inv0 = 1.f / l_i[0], inv1 = 1.f / l_i[1];
    float* ybase = Yg + ((long long)b * SS + step * MM + qt * 64) * DD + h * HDIM;
    #pragma unroll
    for (int j = 0; j < 8; j++) {
        int col = j * 8 + 2 * q;
        float2 v0 = {o[j][0] * inv0, o[j][1] * inv0};
        float2 v1 = {o[j][2] * inv1, o[j][3] * inv1};
        *(float2*)(ybase + (long long)(m0 + g) * DD + col)     = v0;
        *(float2*)(ybase + (long long)(m0 + g + 8) * DD + col) = v1;
    }
}

// ---------------- host orchestration ----------------
static void launch_tc(const float* A,
                      const __nv_bfloat16* h0, const __nv_bfloat16* l0,
                      const __nv_bfloat16* h1, const __nv_bfloat16* l1,
                      const __nv_bfloat16* h2, const __nv_bfloat16* l2,
                      float* C0, float* C1, float* C2,
                      int nsub, int Mtot, int Nper, int K,
                      long long a_bs, int a_off, int Mchunk,
                      long long c_bs, int c_off, int acc)
{
    int nbper = Nper / 64;
    dim3 grid(nsub * nbper, Mtot / 128);
    mma_gemm<<<grid, 256>>>(A, h0, l0, h1, l1, h2, l2, C0, C1, C2,
                            Nper, K, nbper, a_bs, a_off, Mchunk, c_bs, c_off, acc);
}

extern "C" void kernel_launch(void* const* d_in, const int* in_sizes, int n_in,
                              void* d_out, int out_size)
{
    const float* x     = (const float*)d_in[0];
    const float* fcos  = (const float*)d_in[1];
    const float* fsin  = (const float*)d_in[2];
    const float* wq    = (const float*)d_in[3];
    const float* wk    = (const float*)d_in[4];
    const float* wv    = (const float*)d_in[5];
    const float* wo    = (const float*)d_in[6];
    const float* wm    = (const float*)d_in[7];
    const float* wkm   = (const float*)d_in[8];
    const float* wvm   = (const float*)d_in[9];
    const float* w1    = (const float*)d_in[10];
    const float* w3    = (const float*)d_in[11];
    const float* w2    = (const float*)d_in[12];
    const float* ffn_w = (const float*)d_in[13];
    const float* mem_w = (const float*)d_in[14];
    const float* omem  = (const float*)d_in[15];
    float* out = (float*)d_out;

    float *Y, *Qb, *Kb, *Vb, *OM2, *HN, *H1, *H3, *OMN;
    __nv_bfloat16 *PH, *PL;
    cudaGetSymbolAddress((void**)&Y,   g_Y);
    cudaGetSymbolAddress((void**)&Qb,  g_Q);
    cudaGetSymbolAddress((void**)&Kb,  g_K);
    cudaGetSymbolAddress((void**)&Vb,  g_V);
    cudaGetSymbolAddress((void**)&OM2, g_OM2);
    cudaGetSymbolAddress((void**)&HN,  g_HN);
    cudaGetSymbolAddress((void**)&H1,  g_H1);
    cudaGetSymbolAddress((void**)&H3,  g_H3);
    cudaGetSymbolAddress((void**)&OMN, g_OMN);
    cudaGetSymbolAddress((void**)&PH,  g_pk_hi);
    cudaGetSymbolAddress((void**)&PL,  g_pk_lo);

    // repack all weights into n-major bf16 hi/lo tiles
    repack_kernel<<<dim3(32, 16), 256>>>(wq,  PH + OFF_WQ,  PL + OFF_WQ,  DD);
    repack_kernel<<<dim3(32, 16), 256>>>(wk,  PH + OFF_WK,  PL + OFF_WK,  DD);
    repack_kernel<<<dim3(32, 16), 256>>>(wv,  PH + OFF_WV,  PL + OFF_WV,  DD);
    repack_kernel<<<dim3(32, 16), 256>>>(wm,  PH + OFF_WM,  PL + OFF_WM,  DD);
    repack_kernel<<<dim3(32, 16), 256>>>(wkm, PH + OFF_WKM, PL + OFF_WKM, DD);
    repack_kernel<<<dim3(32, 16), 256>>>(wvm, PH + OFF_WVM, PL + OFF_WVM, DD);
    repack_kernel<<<dim3(32, 16), 256>>>(wo,  PH + OFF_WO,  PL + OFF_WO,  DD);
    repack_kernel<<<dim3(32, 44), 256>>>(w1,  PH + OFF_W1,  PL + OFF_W1,  HID);
    repack_kernel<<<dim3(32, 44), 256>>>(w3,  PH + OFF_W3,  PL + OFF_W3,  HID);
    repack_kernel<<<dim3(88, 16), 256>>>(w2,  PH + OFF_W2,  PL + OFF_W2,  DD);

    const long long XBS = (long long)SS * DD;
    const long long LBS = (long long)LL * DD;
    const long long MBS = (long long)MM * DD;

    for (int step = 0; step < NSTEP; step++) {
        launch_tc(x, PH+OFF_WQ, PL+OFF_WQ, PH+OFF_WK, PL+OFF_WK, PH+OFF_WV, PL+OFF_WV,
                  Qb, Kb, Vb, 3, BB*MM, DD, DD, XBS, step*MM, MM, LBS, MM, 0);

        if (step == 0)
            launch_tc(omem, PH+OFF_WM, PL+OFF_WM, 0,0, 0,0, OM2, 0, 0, 1,
                      BB*MM, DD, DD, 0, 0, MM, MBS, 0, 0);
        else
            launch_tc(Y, PH+OFF_WM, PL+OFF_WM, 0,0, 0,0, OM2, 0, 0, 1,
                      BB*MM, DD, DD, XBS, (step-1)*MM, MM, MBS, 0, 0);

        rmsnorm_kernel<<<BB*MM, 256>>>(OM2, ffn_w, HN);
        launch_tc(HN, PH+OFF_W1, PL+OFF_W1, PH+OFF_W3, PL+OFF_W3, 0,0,
                  H1, H3, 0, 2, BB*MM, HID, DD, 0, 0, BB*MM, 0, 0, 0);
        {
            int n4 = BB * MM * HID / 4;
            silu_mul_kernel<<<(n4 + 255) / 256, 256>>>(H1, H3, n4);
        }
        launch_tc(H1, PH+OFF_W2, PL+OFF_W2, 0,0, 0,0, OM2, 0, 0, 1,
                  BB*MM, DD, HID, 0, 0, BB*MM, 0, 0, 1);

        rmsnorm_kernel<<<BB*MM, 256>>>(OM2, mem_w, OMN);

        launch_tc(OMN, PH+OFF_WKM, PL+OFF_WKM, PH+OFF_WVM, PL+OFF_WVM, 0,0,
                  Kb, Vb, 0, 2, BB*MM, DD, DD, MBS, 0, MM, LBS, 0, 0);

        {
            int totK = BB * LL * HH * 32;
            rope_kernel<<<(totK + 255) / 256, 256>>>(Kb, fcos, fsin, 0, LL);
            int totQ = BB * MM * HH * 32;
            rope_kernel<<<(totQ + 255) / 256, 256>>>(Qb, fcos, fsin, MM, MM);
        }

        attn_mma<<<dim3(8, HH, BB), 128>>>(Qb, Kb, Vb, Y, step);
    }

    launch_tc(Y, PH+OFF_WO, PL+OFF_WO, 0,0, 0,0, out, 0, 0, 1,
              BB*SS, DD, DD, 0, 0, BB*SS, 0, 0, 0);
}

// round 6
// speedup vs baseline: 2.9001x; 1.1545x over previous
#include <cuda_runtime.h>
#include <cuda_bf16.h>
#include <math.h>
#include <stdint.h>

// Problem constants
#define BB 2
#define SS 4096
#define DD 1024
#define HH 16
#define HDIM 64
#define MM 512
#define LL 1024          // 2*MM
#define HID 2816
#define NSTEP 8          // SS/MM

// ---------------- scratch (device globals; no allocation allowed) ----------------
__device__ float g_Y  [BB * SS * DD];
__device__ float g_Q  [BB * LL * DD];
__device__ float g_K  [BB * LL * DD];
__device__ float g_V  [BB * LL * DD];
__device__ float g_OM2[BB * MM * DD];
__device__ float g_HN [BB * MM * DD];
__device__ float g_H1 [BB * MM * HID];
__device__ float g_H3 [BB * MM * HID];
__device__ float g_OMN[BB * MM * DD];

// packed bf16 hi/lo weight tiles: (n_blk 64 x k_chunk 32), n-major, 80B row stride.
#define TILE_B 5120
#define PK_SQ  (512 * 2560)
#define PK_W13 (1408 * 2560)
#define PK_W2  (1408 * 2560)
#define PK_TOTAL (7*PK_SQ + 2*PK_W13 + PK_W2)
__device__ __align__(256) __nv_bfloat16 g_pk_hi[PK_TOTAL];
__device__ __align__(256) __nv_bfloat16 g_pk_lo[PK_TOTAL];

#define OFF_WQ  0
#define OFF_WK  (1*PK_SQ)
#define OFF_WV  (2*PK_SQ)
#define OFF_WM  (3*PK_SQ)
#define OFF_WKM (4*PK_SQ)
#define OFF_WVM (5*PK_SQ)
#define OFF_WO  (6*PK_SQ)
#define OFF_W1  (7*PK_SQ)
#define OFF_W3  (7*PK_SQ + PK_W13)
#define OFF_W2  (7*PK_SQ + 2*PK_W13)

// ---------------- mma / ldmatrix helpers (baseline PTX) ----------------
__device__ __forceinline__ void mma16816(float* c, const uint32_t* a, const uint32_t* b) {
    asm volatile(
        "mma.sync.aligned.m16n8k16.row.col.f32.bf16.bf16.f32 "
        "{%0,%1,%2,%3}, {%4,%5,%6,%7}, {%8,%9}, {%0,%1,%2,%3};"
        : "+f"(c[0]), "+f"(c[1]), "+f"(c[2]), "+f"(c[3])
        : "r"(a[0]), "r"(a[1]), "r"(a[2]), "r"(a[3]), "r"(b[0]), "r"(b[1]));
}
__device__ __forceinline__ void ldsm4(uint32_t* r, uint32_t addr) {
    asm volatile("ldmatrix.sync.aligned.m8n8.x4.shared.b16 {%0,%1,%2,%3}, [%4];"
        : "=r"(r[0]), "=r"(r[1]), "=r"(r[2]), "=r"(r[3]) : "r"(addr));
}
__device__ __forceinline__ void ldsm4t(uint32_t* r, uint32_t addr) {
    asm volatile("ldmatrix.sync.aligned.m8n8.x4.trans.shared.b16 {%0,%1,%2,%3}, [%4];"
        : "=r"(r[0]), "=r"(r[1]), "=r"(r[2]), "=r"(r[3]) : "r"(addr));
}
__device__ __forceinline__ uint32_t smem_u32(const void* p) {
    uint32_t a;
    asm("{ .reg .u64 t; cvta.to.shared.u64 t, %1; cvt.u32.u64 %0, t; }" : "=r"(a) : "l"(p));
    return a;
}
__device__ __forceinline__ void splitpack(float x, float y, uint32_t& hi, uint32_t& lo) {
    __nv_bfloat16 hx = __float2bfloat16_rn(x);
    __nv_bfloat16 hy = __float2bfloat16_rn(y);
    __nv_bfloat16 lx = __float2bfloat16_rn(x - __bfloat162float(hx));
    __nv_bfloat16 ly = __float2bfloat16_rn(y - __bfloat162float(hy));
    hi = (uint32_t)__bfloat16_as_ushort(hx) | ((uint32_t)__bfloat16_as_ushort(hy) << 16);
    lo = (uint32_t)__bfloat16_as_ushort(lx) | ((uint32_t)__bfloat16_as_ushort(ly) << 16);
}

// ================= weight repack: fp32 [K,N] -> n-major bf16 hi/lo tiles =================
__device__ __forceinline__ void repack_body(
    const float* __restrict__ W, __nv_bfloat16* __restrict__ Wh,
    __nv_bfloat16* __restrict__ Wl, int N, int KC, int kc, int nb)
{
    __shared__ unsigned char sh[TILE_B];
    __shared__ unsigned char sl[TILE_B];
    for (int e = threadIdx.x; e < 2048; e += 256) {
        int n_l = e & 63, k_l = e >> 6;
        float v = W[(long long)(kc * 32 + k_l) * N + nb * 64 + n_l];
        __nv_bfloat16 h = __float2bfloat16_rn(v);
        __nv_bfloat16 l = __float2bfloat16_rn(v - __bfloat162float(h));
        unsigned off = (unsigned)(n_l * 80 + k_l * 2);
        *(__nv_bfloat16*)(sh + off) = h;
        *(__nv_bfloat16*)(sl + off) = l;
    }
    __syncthreads();
    long long tb = ((long long)nb * KC + kc) * TILE_B;
    uint4* dh = (uint4*)((char*)Wh + tb);
    uint4* dl = (uint4*)((char*)Wl + tb);
    int t = threadIdx.x;
    dh[t] = ((uint4*)sh)[t];
    dl[t] = ((uint4*)sl)[t];
    if (t < 64) {
        dh[256 + t] = ((uint4*)sh)[256 + t];
        dl[256 + t] = ((uint4*)sl)[256 + t];
    }
}

__global__ __launch_bounds__(256) void repack_sq7(
    const float* w0, const float* w1, const float* w2, const float* w3,
    const float* w4, const float* w5, const float* w6,
    __nv_bfloat16* PH, __nv_bfloat16* PL)
{
    int z = blockIdx.z;
    const float* W = (z == 0) ? w0 : (z == 1) ? w1 : (z == 2) ? w2 :
                     (z == 3) ? w3 : (z == 4) ? w4 : (z == 5) ? w5 : w6;
    repack_body(W, PH + (long long)z * PK_SQ, PL + (long long)z * PK_SQ,
                DD, 32, blockIdx.x, blockIdx.y);
}
__global__ __launch_bounds__(256) void repack_w13(
    const float* w1, const float* w3, __nv_bfloat16* PH, __nv_bfloat16* PL)
{
    int z = blockIdx.z;
    repack_body(z ? w3 : w1, PH + OFF_W1 + (long long)z * PK_W13,
                PL + OFF_W1 + (long long)z * PK_W13, HID, 32, blockIdx.x, blockIdx.y);
}
__global__ __launch_bounds__(256) void repack_one(
    const float* W, __nv_bfloat16* Wh, __nv_bfloat16* Wl, int N)
{
    repack_body(W, Wh, Wl, N, gridDim.x, blockIdx.x, blockIdx.y);
}

// ================= mma.sync GEMM, double-buffered + ldmatrix =================
// C[row,col] (+)= A[row,:] @ B, bf16 hi/lo split (AhBh + AhBl + AlBh, fp32 acc).
// CTA tile 128(M) x 64(N), BK=32, 256 threads = 8 warps (mw = w&3, nw = w>>2),
// warp tile 32x32. Multi-output over up to 3 B/C pairs.
#define SA_H 0
#define SA_L 10240
#define SB_H 20480
#define SB_L 25600
#define GBUF 30720

__global__ __launch_bounds__(256, 2) void mma_gemm(
    const float* __restrict__ A,
    const __nv_bfloat16* __restrict__ Bh0, const __nv_bfloat16* __restrict__ Bl0,
    const __nv_bfloat16* __restrict__ Bh1, const __nv_bfloat16* __restrict__ Bl1,
    const __nv_bfloat16* __restrict__ Bh2, const __nv_bfloat16* __restrict__ Bl2,
    float* __restrict__ C0, float* __restrict__ C1, float* __restrict__ C2,
    int Nper, int K, int nbper,
    long long a_bs, int a_off, int Mchunk,
    long long c_bs, int c_off, int acc)
{
    extern __shared__ __align__(16) unsigned char smem[];
    uint32_t sb = smem_u32(smem);

    int tid = threadIdx.x;
    int wid = tid >> 5, lane = tid & 31;
    int g = lane >> 2, q = lane & 3;
    int mw = wid & 3, nw = wid >> 2;
    int rowin = lane & 7, l8 = (lane >> 3) & 1, l16 = (lane >> 4) & 1;

    int sel = blockIdx.x / nbper;
    int n_blk = blockIdx.x - sel * nbper;
    int block_n = n_blk * 64;
    int block_m = blockIdx.y * 128;
    const __nv_bfloat16* Bh = (sel == 0) ? Bh0 : ((sel == 1) ? Bh1 : Bh2);
    const __nv_bfloat16* Bl = (sel == 0) ? Bl0 : ((sel == 1) ? Bl1 : Bl2);
    float*               C  = (sel == 0) ? C0  : ((sel == 1) ? C1  : C2);

    int nk = K >> 5;

    // loader addressing (same layouts as verified R4 kernel)
    const float* aptr[4];
    unsigned     ast_off[4];
    #pragma unroll
    for (int j = 0; j < 4; j++) {
        int f = tid + j * 256;
        int row = f >> 3, c4 = f & 7;
        int gr = block_m + row;
        aptr[j] = A + (long long)(gr / Mchunk) * a_bs
                    + (long long)((gr % Mchunk) + a_off) * K + c4 * 4;
        ast_off[j] = (unsigned)(row * 80 + c4 * 8);
    }
    const char* bh_src = (const char*)Bh + (long long)n_blk * nk * TILE_B;
    const char* bl_src = (const char*)Bl + (long long)n_blk * nk * TILE_B;

    // ldmatrix per-lane fragment addresses (byte offsets within a buffer)
    unsigned a_frag_off[2], b_frag_off[2];
    #pragma unroll
    for (int i = 0; i < 2; i++)
        a_frag_off[i] = (unsigned)((mw * 32 + i * 16 + rowin + l8 * 8) * 80 + l16 * 16);
    #pragma unroll
    for (int jp = 0; jp < 2; jp++)
        b_frag_off[jp] = (unsigned)((nw * 32 + jp * 16 + rowin + l16 * 8) * 80 + l8 * 16);

    float c[2][4][4];
    #pragma unroll
    for (int i = 0; i < 2; i++)
        #pragma unroll
        for (int j = 0; j < 4; j++)
            #pragma unroll
            for (int e = 0; e < 4; e++) c[i][j][e] = 0.f;

    // prefetch chunk 0
    float4 pa[4];
    uint4 pbh0, pbh1, pbl0, pbl1;
    #pragma unroll
    for (int j = 0; j < 4; j++) pa[j] = *(const float4*)(aptr[j]);
    pbh0 = *(const uint4*)(bh_src + tid * 16);
    pbl0 = *(const uint4*)(bl_src + tid * 16);
    if (tid < 64) {
        pbh1 = *(const uint4*)(bh_src + (256 + tid) * 16);
        pbl1 = *(const uint4*)(bl_src + (256 + tid) * 16);
    }

    // store chunk 0 into buffer 0
    {
        uint32_t base = 0;
        #pragma unroll
        for (int j = 0; j < 4; j++) {
            float4 v = pa[j];
            uint2 hv, lv;
            splitpack(v.x, v.y, hv.x, lv.x);
            splitpack(v.z, v.w, hv.y, lv.y);
            *(uint2*)(smem + base + SA_H + ast_off[j]) = hv;
            *(uint2*)(smem + base + SA_L + ast_off[j]) = lv;
        }
        *(uint4*)(smem + base + SB_H + tid * 16) = pbh0;
        *(uint4*)(smem + base + SB_L + tid * 16) = pbl0;
        if (tid < 64) {
            *(uint4*)(smem + base + SB_H + (256 + tid) * 16) = pbh1;
            *(uint4*)(smem + base + SB_L + (256 + tid) * 16) = pbl1;
        }
    }
    __syncthreads();

    int cur = 0;
    for (int it = 0; it < nk; it++) {
        bool hn = (it + 1 < nk);
        if (hn) {   // issue global prefetch first; latency hidden by compute
            #pragma unroll
            for (int j = 0; j < 4; j++) pa[j] = *(const float4*)(aptr[j] + (it + 1) * 32);
            long long bo = (long long)(it + 1) * TILE_B;
            pbh0 = *(const uint4*)(bh_src + bo + tid * 16);
            pbl0 = *(const uint4*)(bl_src + bo + tid * 16);
            if (tid < 64) {
                pbh1 = *(const uint4*)(bh_src + bo + (256 + tid) * 16);
                pbl1 = *(const uint4*)(bl_src + bo + (256 + tid) * 16);
            }
        }

        // compute from buffer cur
        uint32_t abh = sb + cur * GBUF + SA_H;
        uint32_t abl = sb + cur * GBUF + SA_L;
        uint32_t bbh = sb + cur * GBUF + SB_H;
        uint32_t bbl = sb + cur * GBUF + SB_L;
        #pragma unroll
        for (int kk = 0; kk < 2; kk++) {
            int kb = kk * 32;
            uint32_t ah[2][4], al[2][4], bh[2][4], bl[2][4];
            #pragma unroll
            for (int i = 0; i < 2; i++) {
                ldsm4(ah[i], abh + a_frag_off[i] + kb);
                ldsm4(al[i], abl + a_frag_off[i] + kb);
            }
            #pragma unroll
            for (int jp = 0; jp < 2; jp++) {
                ldsm4(bh[jp], bbh + b_frag_off[jp] + kb);
                ldsm4(bl[jp], bbl + b_frag_off[jp] + kb);
            }
            #pragma unroll
            for (int i = 0; i < 2; i++)
                #pragma unroll
                for (int jp = 0; jp < 2; jp++) {
                    mma16816(c[i][jp*2],   ah[i], &bh[jp][0]);
                    mma16816(c[i][jp*2],   ah[i], &bl[jp][0]);
                    mma16816(c[i][jp*2],   al[i], &bh[jp][0]);
                    mma16816(c[i][jp*2+1], ah[i], &bh[jp][2]);
                    mma16816(c[i][jp*2+1], ah[i], &bl[jp][2]);
                    mma16816(c[i][jp*2+1], al[i], &bh[jp][2]);
                }
        }

        if (hn) {
            uint32_t base = (cur ^ 1) * GBUF;
            #pragma unroll
            for (int j = 0; j < 4; j++) {
                float4 v = pa[j];
                uint2 hv, lv;
                splitpack(v.x, v.y, hv.x, lv.x);
                splitpack(v.z, v.w, hv.y, lv.y);
                *(uint2*)(smem + base + SA_H + ast_off[j]) = hv;
                *(uint2*)(smem + base + SA_L + ast_off[j]) = lv;
            }
            *(uint4*)(smem + base + SB_H + tid * 16) = pbh0;
            *(uint4*)(smem + base + SB_L + tid * 16) = pbl0;
            if (tid < 64) {
                *(uint4*)(smem + base + SB_H + (256 + tid) * 16) = pbh1;
                *(uint4*)(smem + base + SB_L + (256 + tid) * 16) = pbl1;
            }
            __syncthreads();
            cur ^= 1;
        }
    }

    // epilogue (unchanged)
    #pragma unroll
    for (int i = 0; i < 2; i++) {
        int row0 = block_m + mw * 32 + i * 16 + g;
        #pragma unroll
        for (int half = 0; half < 2; half++) {
            int gr = row0 + half * 8;
            float* crow = C + (long long)(gr / Mchunk) * c_bs
                            + (long long)((gr % Mchunk) + c_off) * Nper + block_n;
            #pragma unroll
            for (int j = 0; j < 4; j++) {
                int col = nw * 32 + j * 8 + 2 * q;
                float2 v;
                v.x = c[i][j][half * 2 + 0];
                v.y = c[i][j][half * 2 + 1];
                if (acc) {
                    float2 o = *(float2*)(crow + col);
                    v.x += o.x; v.y += o.y;
                }
                *(float2*)(crow + col) = v;
            }
        }
    }
}

// ---------------- RMSNorm ----------------
__global__ __launch_bounds__(256) void rmsnorm_kernel(
    const float* __restrict__ X, const float* __restrict__ W, float* __restrict__ O)
{
    int row = blockIdx.x;
    int t = threadIdx.x;
    const float4* x = (const float4*)(X + (long long)row * DD);
    float4 xv = x[t];
    float ss = xv.x*xv.x + xv.y*xv.y + xv.z*xv.z + xv.w*xv.w;
    #pragma unroll
    for (int off = 16; off >= 1; off >>= 1)
        ss += __shfl_xor_sync(0xffffffffu, ss, off);
    __shared__ float red[8];
    if ((t & 31) == 0) red[t >> 5] = ss;
    __syncthreads();
    __shared__ float s_inv;
    if (t == 0) {
        float tot = 0.f;
        #pragma unroll
        for (int i = 0; i < 8; i++) tot += red[i];
        s_inv = rsqrtf(tot * (1.0f / DD) + 1e-5f);
    }
    __syncthreads();
    float inv = s_inv;
    float4 wv = ((const float4*)W)[t];
    float4 ov = {xv.x*inv*wv.x, xv.y*inv*wv.y, xv.z*inv*wv.z, xv.w*inv*wv.w};
    ((float4*)(O + (long long)row * DD))[t] = ov;
}

// ---------------- SwiGLU ----------------
__global__ void silu_mul_kernel(float* __restrict__ h1, const float* __restrict__ h3, int n4)
{
    int i = blockIdx.x * blockDim.x + threadIdx.x;
    if (i >= n4) return;
    float4 a = ((float4*)h1)[i];
    float4 b = ((const float4*)h3)[i];
    a.x = a.x / (1.f + expf(-a.x)) * b.x;
    a.y = a.y / (1.f + expf(-a.y)) * b.y;
    a.z = a.z / (1.f + expf(-a.z)) * b.z;
    a.w = a.w / (1.f + expf(-a.w)) * b.w;
    ((float4*)h1)[i] = a;
}

// ---------------- RoPE ----------------
__global__ void rope_kernel(float* __restrict__ T, const float* __restrict__ fcos,
                            const float* __restrict__ fsin, int l_begin, int l_count)
{
    int idx = blockIdx.x * blockDim.x + threadIdx.x;
    int total = BB * l_count * HH * (HDIM / 2);
    if (idx >= total) return;
    int i = idx & 31;
    int h = (idx >> 5) & 15;
    int rest = idx >> 9;
    int lr = rest % l_count;
    int b = rest / l_count;
    int l = l_begin + lr;
    float* p = T + ((long long)b * LL + l) * DD + h * HDIM + 2 * i;
    float c = fcos[l * 32 + i];
    float s = fsin[l * 32 + i];
    float2 v = *(float2*)p;
    float2 o = {v.x * c - v.y * s, v.x * s + v.y * c};
    *(float2*)p = o;
}

// ---------------- Flash attention, tensor-core (mma.sync + ldmatrix) ----------------
// grid (8 qt, 16 h, 2 b), 128 threads = 4 warps; warp w owns q-rows w*16..w*16+15.
// smem: K hi/lo + V hi/lo, 64 rows x 144B stride. V row-major, V^T frags via ldsm.trans.
#define AKH 0
#define AKL 9216
#define AVH 18432
#define AVL 27648

__global__ __launch_bounds__(128) void attn_mma(
    const float* __restrict__ Qg, const float* __restrict__ Kg, const float* __restrict__ Vg,
    float* __restrict__ Yg, int step)
{
    __shared__ __align__(16) unsigned char sm[36864];
    uint32_t sb = smem_u32(sm);

    int qt = blockIdx.x, h = blockIdx.y, b = blockIdx.z;
    int tid = threadIdx.x;
    int w = tid >> 5, lane = tid & 31;
    int g = lane >> 2, q = lane & 3;
    int m0 = w << 4;
    int rowin = lane & 7, l8 = (lane >> 3) & 1, l16 = (lane >> 4) & 1;

    int r  = tid >> 1;            // 0..63
    int ch = (tid & 1) << 5;      // 0 or 32

    // ldmatrix fragment offsets
    unsigned koff[4], voff[4];
    #pragma unroll
    for (int jp = 0; jp < 4; jp++) {
        koff[jp] = (unsigned)((jp * 16 + l16 * 8 + rowin) * 144 + l8 * 16);
        voff[jp] = (unsigned)((l8 * 8 + rowin) * 144 + (jp * 16 + l16 * 8) * 2);
    }

    // ---- stage Q (scaled) into K region, lift fragments to registers ----
    {
        const float* src = Qg + ((long long)b * LL + MM + qt * 64 + r) * DD + h * HDIM + ch;
        #pragma unroll
        for (int i = 0; i < 8; i++) {
            float4 v = *(const float4*)(src + i * 4);
            v.x *= 0.125f; v.y *= 0.125f; v.z *= 0.125f; v.w *= 0.125f;
            uint2 hv, lv;
            splitpack(v.x, v.y, hv.x, lv.x);
            splitpack(v.z, v.w, hv.y, lv.y);
            unsigned off = (unsigned)(r * 144 + (ch + i * 4) * 2);
            *(uint2*)(sm + AKH + off) = hv;
            *(uint2*)(sm + AKL + off) = lv;
        }
    }
    __syncthreads();
    uint32_t qh[4][4], ql[4][4];
    #pragma unroll
    for (int ks = 0; ks < 4; ks++) {
        int kb = ks * 32 + q * 4;
        int r0 = (m0 + g) * 144 + kb, r1 = r0 + 8 * 144;
        qh[ks][0] = *(const uint32_t*)(sm + AKH + r0);
        qh[ks][1] = *(const uint32_t*)(sm + AKH + r1);
        qh[ks][2] = *(const uint32_t*)(sm + AKH + r0 + 16);
        qh[ks][3] = *(const uint32_t*)(sm + AKH + r1 + 16);
        ql[ks][0] = *(const uint32_t*)(sm + AKL + r0);
        ql[ks][1] = *(const uint32_t*)(sm + AKL + r1);
        ql[ks][2] = *(const uint32_t*)(sm + AKL + r0 + 16);
        ql[ks][3] = *(const uint32_t*)(sm + AKL + r1 + 16);
    }

    float m_i[2] = {-1e30f, -1e30f}, l_i[2] = {0.f, 0.f};
    float o[8][4];
    #pragma unroll
    for (int j = 0; j < 8; j++)
        #pragma unroll
        for (int e = 0; e < 4; e++) o[j][e] = 0.f;

    int nkt = 9 + qt;
    for (int kt = 0; kt < nkt; kt++) {
        __syncthreads();

        // load K and V tiles (both row-major, vectorized)
        const float* ksrc = Kg + ((long long)b * LL + kt * 64 + r) * DD + h * HDIM + ch;
        const float* vsrc = Vg + ((long long)b * LL + kt * 64 + r) * DD + h * HDIM + ch;
        #pragma unroll
        for (int i = 0; i < 8; i++) {
            unsigned off = (unsigned)(r * 144 + (ch + i * 4) * 2);
            float4 kv = *(const float4*)(ksrc + i * 4);
            uint2 hv, lv;
            splitpack(kv.x, kv.y, hv.x, lv.x);
            splitpack(kv.z, kv.w, hv.y, lv.y);
            *(uint2*)(sm + AKH + off) = hv;
            *(uint2*)(sm + AKL + off) = lv;

            float4 vv = *(const float4*)(vsrc + i * 4);
            splitpack(vv.x, vv.y, hv.x, lv.x);
            splitpack(vv.z, vv.w, hv.y, lv.y);
            *(uint2*)(sm + AVH + off) = hv;
            *(uint2*)(sm + AVL + off) = lv;
        }
        __syncthreads();

        // ---- S = Q K^T ----
        float s[8][4];
        #pragma unroll
        for (int j = 0; j < 8; j++)
            #pragma unroll
            for (int e = 0; e < 4; e++) s[j][e] = 0.f;

        #pragma unroll
        for (int ks = 0; ks < 4; ks++) {
            #pragma unroll
            for (int jp = 0; jp < 4; jp++) {
                uint32_t bh[4], bl[4];
                ldsm4(bh, sb + AKH + koff[jp] + ks * 32);
                ldsm4(bl, sb + AKL + koff[jp] + ks * 32);
                mma16816(s[jp*2],   qh[ks], &bh[0]);
                mma16816(s[jp*2],   qh[ks], &bl[0]);
                mma16816(s[jp*2],   ql[ks], &bh[0]);
                mma16816(s[jp*2+1], qh[ks], &bh[2]);
                mma16816(s[jp*2+1], qh[ks], &bl[2]);
                mma16816(s[jp*2+1], ql[ks], &bh[2]);
            }
        }

        // causal mask on diagonal tile
        if (kt == nkt - 1) {
            #pragma unroll
            for (int j = 0; j < 8; j++)
                #pragma unroll
                for (int e = 0; e < 4; e++) {
                    int col = j * 8 + 2 * q + (e & 1);
                    int row = m0 + g + ((e >> 1) << 3);
                    if (col > row) s[j][e] = -1e30f;
                }
        }

        // ---- online softmax ----
        float mx0 = -1e30f, mx1 = -1e30f;
        #pragma unroll
        for (int j = 0; j < 8; j++) {
            mx0 = fmaxf(mx0, fmaxf(s[j][0], s[j][1]));
            mx1 = fmaxf(mx1, fmaxf(s[j][2], s[j][3]));
        }
        mx0 = fmaxf(mx0, __shfl_xor_sync(0xffffffffu, mx0, 1));
        mx0 = fmaxf(mx0, __shfl_xor_sync(0xffffffffu, mx0, 2));
        mx1 = fmaxf(mx1, __shfl_xor_sync(0xffffffffu, mx1, 1));
        mx1 = fmaxf(mx1, __shfl_xor_sync(0xffffffffu, mx1, 2));
        float mn0 = fmaxf(m_i[0], mx0), mn1 = fmaxf(m_i[1], mx1);
        float al0 = expf(m_i[0] - mn0), al1 = expf(m_i[1] - mn1);
        float sum0 = 0.f, sum1 = 0.f;
        #pragma unroll
        for (int j = 0; j < 8; j++) {
            s[j][0] = expf(s[j][0] - mn0);
            s[j][1] = expf(s[j][1] - mn0);
            s[j][2] = expf(s[j][2] - mn1);
            s[j][3] = expf(s[j][3] - mn1);
            sum0 += s[j][0] + s[j][1];
            sum1 += s[j][2] + s[j][3];
        }
        sum0 += __shfl_xor_sync(0xffffffffu, sum0, 1);
        sum0 += __shfl_xor_sync(0xffffffffu, sum0, 2);
        sum1 += __shfl_xor_sync(0xffffffffu, sum1, 1);
        sum1 += __shfl_xor_sync(0xffffffffu, sum1, 2);
        l_i[0] = l_i[0] * al0 + sum0;  m_i[0] = mn0;
        l_i[1] = l_i[1] * al1 + sum1;  m_i[1] = mn1;
        #pragma unroll
        for (int j = 0; j < 8; j++) {
            o[j][0] *= al0; o[j][1] *= al0;
            o[j][2] *= al1; o[j][3] *= al1;
        }

        // ---- O += P V  (V^T frags via ldmatrix.trans) ----
        #pragma unroll
        for (int ks = 0; ks < 4; ks++) {
            uint32_t pah[4], pal[4];
            splitpack(s[2*ks][0],   s[2*ks][1],   pah[0], pal[0]);
            splitpack(s[2*ks][2],   s[2*ks][3],   pah[1], pal[1]);
            splitpack(s[2*ks+1][0], s[2*ks+1][1], pah[2], pal[2]);
            splitpack(s[2*ks+1][2], s[2*ks+1][3], pah[3], pal[3]);
            #pragma unroll
            for (int jp = 0; jp < 4; jp++) {
                uint32_t vh[4], vl[4];
                ldsm4t(vh, sb + AVH + voff[jp] + ks * 2304);
                ldsm4t(vl, sb + AVL + voff[jp] + ks * 2304);
                mma16816(o[jp*2],   pah, &vh[0]);
                mma16816(o[jp*2],   pah, &vl[0]);
                mma16816(o[jp*2],   pal, &vh[0]);
                mma16816(o[jp*2+1], pah, &vh[2]);
                mma16816(o[jp*2+1], pah, &vl[2]);
                mma16816(o[jp*2+1], pal, &vh[2]);
            }
        }
    }

    // ---- write normalized output ----
    float inv0 = 1.f / l_i[0], inv1 = 1.f / l_i[1];
    float* ybase = Yg + ((long long)b * SS + step * MM + qt * 64) * DD + h * HDIM;
    #pragma unroll
    for (int j = 0; j < 8; j++) {
        int col = j * 8 + 2 * q;
        float2 v0 = {o[j][0] * inv0, o[j][1] * inv0};
        float2 v1 = {o[j][2] * inv1, o[j][3] * inv1};
        *(float2*)(ybase + (long long)(m0 + g) * DD + col)     = v0;
        *(float2*)(ybase + (long long)(m0 + g + 8) * DD + col) = v1;
    }
}

// ---------------- host orchestration ----------------
static void launch_tc(const float* A,
                      const __nv_bfloat16* h0, const __nv_bfloat16* l0,
                      const __nv_bfloat16* h1, const __nv_bfloat16* l1,
                      const __nv_bfloat16* h2, const __nv_bfloat16* l2,
                      float* C0, float* C1, float* C2,
                      int nsub, int Mtot, int Nper, int K,
                      long long a_bs, int a_off, int Mchunk,
                      long long c_bs, int c_off, int acc)
{
    int nbper = Nper / 64;
    dim3 grid(nsub * nbper, Mtot / 128);
    mma_gemm<<<grid, 256, 2 * GBUF>>>(A, h0, l0, h1, l1, h2, l2, C0, C1, C2,
                                      Nper, K, nbper, a_bs, a_off, Mchunk, c_bs, c_off, acc);
}

extern "C" void kernel_launch(void* const* d_in, const int* in_sizes, int n_in,
                              void* d_out, int out_size)
{
    const float* x     = (const float*)d_in[0];
    const float* fcos  = (const float*)d_in[1];
    const float* fsin  = (const float*)d_in[2];
    const float* wq    = (const float*)d_in[3];
    const float* wk    = (const float*)d_in[4];
    const float* wv    = (const float*)d_in[5];
    const float* wo    = (const float*)d_in[6];
    const float* wm    = (const float*)d_in[7];
    const float* wkm   = (const float*)d_in[8];
    const float* wvm   = (const float*)d_in[9];
    const float* w1    = (const float*)d_in[10];
    const float* w3    = (const float*)d_in[11];
    const float* w2    = (const float*)d_in[12];
    const float* ffn_w = (const float*)d_in[13];
    const float* mem_w = (const float*)d_in[14];
    const float* omem  = (const float*)d_in[15];
    float* out = (float*)d_out;

    cudaFuncSetAttribute(mma_gemm, cudaFuncAttributeMaxDynamicSharedMemorySize, 2 * GBUF);

    float *Y, *Qb, *Kb, *Vb, *OM2, *HN, *H1, *H3, *OMN;
    __nv_bfloat16 *PH, *PL;
    cudaGetSymbolAddress((void**)&Y,   g_Y);
    cudaGetSymbolAddress((void**)&Qb,  g_Q);
    cudaGetSymbolAddress((void**)&Kb,  g_K);
    cudaGetSymbolAddress((void**)&Vb,  g_V);
    cudaGetSymbolAddress((void**)&OM2, g_OM2);
    cudaGetSymbolAddress((void**)&HN,  g_HN);
    cudaGetSymbolAddress((void**)&H1,  g_H1);
    cudaGetSymbolAddress((void**)&H3,  g_H3);
    cudaGetSymbolAddress((void**)&OMN, g_OMN);
    cudaGetSymbolAddress((void**)&PH,  g_pk_hi);
    cudaGetSymbolAddress((void**)&PL,  g_pk_lo);

    // repack weights (3 launches)
    repack_sq7<<<dim3(32, 16, 7), 256>>>(wq, wk, wv, wm, wkm, wvm, wo, PH, PL);
    repack_w13<<<dim3(32, 44, 2), 256>>>(w1, w3, PH, PL);
    repack_one<<<dim3(88, 16), 256>>>(w2, PH + OFF_W2, PL + OFF_W2, DD);

    const long long XBS = (long long)SS * DD;
    const long long LBS = (long long)LL * DD;
    const long long MBS = (long long)MM * DD;

    for (int step = 0; step < NSTEP; step++) {
        launch_tc(x, PH+OFF_WQ, PL+OFF_WQ, PH+OFF_WK, PL+OFF_WK, PH+OFF_WV, PL+OFF_WV,
                  Qb, Kb, Vb, 3, BB*MM, DD, DD, XBS, step*MM, MM, LBS, MM, 0);

        if (step == 0)
            launch_tc(omem, PH+OFF_WM, PL+OFF_WM, 0,0, 0,0, OM2, 0, 0, 1,
                      BB*MM, DD, DD, 0, 0, MM, MBS, 0, 0);
        else
            launch_tc(Y, PH+OFF_WM, PL+OFF_WM, 0,0, 0,0, OM2, 0, 0, 1,
                      BB*MM, DD, DD, XBS, (step-1)*MM, MM, MBS, 0, 0);

        rmsnorm_kernel<<<BB*MM, 256>>>(OM2, ffn_w, HN);
        launch_tc(HN, PH+OFF_W1, PL+OFF_W1, PH+OFF_W3, PL+OFF_W3, 0,0,
                  H1, H3, 0, 2, BB*MM, HID, DD, 0, 0, BB*MM, 0, 0, 0);
        {
            int n4 = BB * MM * HID / 4;
            silu_mul_kernel<<<(n4 + 255) / 256, 256>>>(H1, H3, n4);
        }
        launch_tc(H1, PH+OFF_W2, PL+OFF_W2, 0,0, 0,0, OM2, 0, 0, 1,
                  BB*MM, DD, HID, 0, 0, BB*MM, 0, 0, 1);

        rmsnorm_kernel<<<BB*MM, 256>>>(OM2, mem_w, OMN);

        launch_tc(OMN, PH+OFF_WKM, PL+OFF_WKM, PH+OFF_WVM, PL+OFF_WVM, 0,0,
                  Kb, Vb, 0, 2, BB*MM, DD, DD, MBS, 0, MM, LBS, 0, 0);

        {
            int totK = BB * LL * HH * 32;
            rope_kernel<<<(totK + 255) / 256, 256>>>(Kb, fcos, fsin, 0, LL);
            int totQ = BB * MM * HH * 32;
            rope_kernel<<<(totQ + 255) / 256, 256>>>(Qb, fcos, fsin, MM, MM);
        }

        attn_mma<<<dim3(8, HH, BB), 128>>>(Qb, Kb, Vb, Y, step);
    }

    launch_tc(Y, PH+OFF_WO, PL+OFF_WO, 0,0, 0,0, out, 0, 0, 1,
              BB*SS, DD, DD, 0, 0, BB*SS, 0, 0, 0);
}